// round 4
// baseline (speedup 1.0000x reference)
#include <cuda_runtime.h>

typedef unsigned long long u64;

// ---------------------------------------------------------------------------
// Shapes: B=8, C=64, N=512, T=64, valid L=58 (stored padded to 64).
// Buffers: q0..q9 (ids 0-9), R0=10, R1=11, ACC=12, H=13. Each 8*64*512*64 fp32.
// ---------------------------------------------------------------------------
#define BUFSZ (8ULL*64ULL*512ULL*64ULL)

__device__ float g_pool[14ULL*BUFSZ];

__device__ float g_An [512*512];   // [w][v]: g_An[w*512+v] = M1[v][w]
__device__ float g_AnT[512*512];   // [w][v]: g_AnT[w*512+v] = M2[v][w]
__device__ float g_rd1[512], g_rd2[512];
__device__ float g_W7[448*128];    // [kd][o], kd = c*7+tau, o = br*64+j*16+oc
__device__ float g_b7[128];
__device__ float g_Wq[10*64*64];   // [m][cp][c]
__device__ float g_bias[64];

// ---------------------------------------------------------------------------
// packed fp32x2 FMA helpers (Blackwell FFMA2)
// ---------------------------------------------------------------------------
__device__ __forceinline__ u64 dup2(float a){
    u64 r; asm("mov.b64 %0, {%1,%1};" : "=l"(r) : "f"(a)); return r;
}
__device__ __forceinline__ void ffma2(u64 &d, u64 a, u64 b){
    asm("fma.rn.f32x2 %0, %1, %2, %0;" : "+l"(d) : "l"(a), "l"(b));
}
__device__ __forceinline__ float2 unpk(u64 u){
    union { u64 u; float2 f; } c; c.u = u; return c.f;
}

// 32-step k-chunk. As: [kk][128] fp32 (conflict-free LDS.128 per 4 rows),
// Bs: [kk][64] fp32 (warp-broadcast u64 pairs over adjacent l).
// Thread (tv,tl): rows tv*4..+3, l = tl*8..+7 as 4 pairs. acc[16] = f32x2.
__device__ __forceinline__ void gemm32(const float* __restrict__ As,
                                       const float* __restrict__ Bs,
                                       int tv, int tl, u64* acc){
#pragma unroll 8
    for (int kk = 0; kk < 32; ++kk){
        float4 av = *(const float4*)(As + kk*128 + (tv<<2));
        const u64* bp = (const u64*)(Bs + (kk<<6) + (tl<<3));
        u64 a0=dup2(av.x), a1=dup2(av.y), a2=dup2(av.z), a3=dup2(av.w);
        u64 b0=bp[0], b1=bp[1], b2=bp[2], b3=bp[3];
        ffma2(acc[ 0],a0,b0); ffma2(acc[ 1],a0,b1); ffma2(acc[ 2],a0,b2); ffma2(acc[ 3],a0,b3);
        ffma2(acc[ 4],a1,b0); ffma2(acc[ 5],a1,b1); ffma2(acc[ 6],a1,b2); ffma2(acc[ 7],a1,b3);
        ffma2(acc[ 8],a2,b0); ffma2(acc[ 9],a2,b1); ffma2(acc[10],a2,b2); ffma2(acc[11],a2,b3);
        ffma2(acc[12],a3,b0); ffma2(acc[13],a3,b1); ffma2(acc[14],a3,b2); ffma2(acc[15],a3,b3);
    }
}

// ---------------------------------------------------------------------------
// degrees
// ---------------------------------------------------------------------------
__global__ void k_deg(const float* __restrict__ adj){
    int v = blockIdx.x, tid = threadIdx.x;
    float s1 = 0.f, s2 = 0.f;
    for (int w = tid; w < 512; w += 256){
        s1 += adj[v*512 + w];
        s2 += adj[w*512 + v];
    }
    __shared__ float r1[256], r2[256];
    r1[tid] = s1; r2[tid] = s2;
    __syncthreads();
    for (int s = 128; s > 0; s >>= 1){
        if (tid < s){ r1[tid] += r1[tid+s]; r2[tid] += r2[tid+s]; }
        __syncthreads();
    }
    if (tid == 0){
        g_rd1[v] = rsqrtf(r1[0] + 1.f);
        g_rd2[v] = rsqrtf(r2[0] + 1.f);
    }
}

__global__ void k_norm(const float* __restrict__ adj){
    int w = blockIdx.x;
    float dw1 = g_rd1[w], dw2 = g_rd2[w];
    for (int v = threadIdx.x; v < 512; v += 256){
        float e = (v == w) ? 1.f : 0.f;
        g_An [w*512 + v] = g_rd1[v] * (adj[v*512 + w] + e) * dw1;
        g_AnT[w*512 + v] = g_rd2[v] * (adj[w*512 + v] + e) * dw2;
    }
}

// ---------------------------------------------------------------------------
// prep: pad inception weights to k=7 (windows end at l+6), build W'_j (Horner)
// ---------------------------------------------------------------------------
__global__ void k_prep(const float* i1w0,const float* i1b0,const float* i1w1,const float* i1b1,
                       const float* i1w2,const float* i1b2,const float* i1w3,const float* i1b3,
                       const float* i2w0,const float* i2b0,const float* i2w1,const float* i2b1,
                       const float* i2w2,const float* i2b2,const float* i2w3,const float* i2b3,
                       const float* m1w,const float* m1b,const float* m2w,const float* m2b){
    int g0 = blockIdx.x*256 + threadIdx.x, gstr = gridDim.x*256;
    const float* WS[8] = {i1w0,i1w1,i1w2,i1w3,i2w0,i2w1,i2w2,i2w3};
    const float* BS[8] = {i1b0,i1b1,i1b2,i1b3,i2b0,i2b1,i2b2,i2b3};
    const int KERN[4] = {2,3,6,7};

    for (int idx = g0; idx < 448*128; idx += gstr){
        int kd = idx >> 7, o = idx & 127;
        int c = kd / 7, tau = kd - c*7;
        int br = o >> 6, j = (o >> 4) & 3, oc = o & 15;
        int k = KERN[j];
        int t = tau - (7 - k);
        g_W7[idx] = (t >= 0) ? WS[br*4 + j][(oc*64 + c)*k + t] : 0.f;
    }
    for (int idx = g0; idx < 128; idx += gstr){
        int br = idx >> 6, j = (idx >> 4) & 3, oc = idx & 15;
        g_b7[idx] = BS[br*4 + j][oc];
    }
    for (int idx = g0; idx < 64; idx += gstr)
        g_bias[idx] = m1b[idx] + m2b[idx];

    // coefficient of L^j in concat block g = [x, y2, y3, y4, yf]
    const float COEF[5][5] = {
        {1.f, 1.f,      1.f,      1.f,      1.f     },
        {0.f, 1.f/3.f,  2.f/3.f,  1.f,      1.f     },
        {0.f, 0.f,      1.f/3.f,  1.f/3.f,  0.5f    },
        {0.f, 0.f,      0.f,      1.f/3.f,  1.f/6.f },
        {0.f, 0.f,      0.f,      0.f,      1.f/24.f}};
    for (int idx = g0; idx < 10*4096; idx += gstr){
        int m = idx >> 12, cp = (idx >> 6) & 63, c = idx & 63;
        int j = m % 5;
        const float* mw = (m < 5) ? m1w : m2w;
        float s = 0.f;
#pragma unroll
        for (int g = 0; g < 5; ++g)
            s += COEF[j][g] * mw[c*320 + g*64 + cp];
        g_Wq[idx] = s;
    }
}

// ---------------------------------------------------------------------------
// inception: per (b,n) GEMM [128 o x 448] x [448 x 64 l] with fused gate
// rows 0..63 -> tanh, 64..127 -> sigmoid; h = tanh*sig  -> buffer 13
// ---------------------------------------------------------------------------
__global__ __launch_bounds__(256) void k_incept(const float* __restrict__ x){
    __shared__ __align__(16) float As[32*128];   // 16KB (gate overlay reuses it)
    __shared__ __align__(16) float Bs[32*64];    // 8KB
    int bn = blockIdx.x;
    int b = bn >> 9, n = bn & 511;
    int tid = threadIdx.x, tv = tid & 31, tl = tid >> 5;
    const float* xb = x + (u64)b*64*512*64 + (u64)n*64;

    u64 acc[16];
#pragma unroll
    for (int i = 0; i < 16; ++i) acc[i] = 0ULL;

    for (int w0 = 0; w0 < 448; w0 += 32){
#pragma unroll
        for (int i = 0; i < 16; ++i){
            int idx = i*256 + tid;
            As[idx] = g_W7[w0*128 + idx];
        }
#pragma unroll
        for (int i = 0; i < 8; ++i){
            int idx = i*256 + tid;
            int kd = w0 + (idx >> 6), l = idx & 63;
            int c = kd / 7, tau = kd - c*7;
            int t = l + tau;
            Bs[idx] = (t < 64) ? xb[(u64)c*32768 + t] : 0.f;
        }
        __syncthreads();
        gemm32(As, Bs, tv, tl, acc);
        __syncthreads();
    }

    float* gs = As;   // 64x64 sigmoid overlay (exactly 16KB)
    if (tv >= 16){
#pragma unroll
        for (int i = 0; i < 4; ++i){
            int o = tv*4 + i;           // 64..127
            int gc = o - 64;
            float bia = g_b7[o];
#pragma unroll
            for (int j = 0; j < 4; ++j){
                float2 s = unpk(acc[i*4 + j]);
                float2 g;
                g.x = 1.f/(1.f + expf(-(s.x + bia)));
                g.y = 1.f/(1.f + expf(-(s.y + bia)));
                *(float2*)(gs + gc*64 + tl*8 + 2*j) = g;
            }
        }
    }
    __syncthreads();
    if (tv < 16){
        float* hbuf = g_pool + 13ULL*BUFSZ;
#pragma unroll
        for (int i = 0; i < 4; ++i){
            int o = tv*4 + i;           // 0..63
            float bia = g_b7[o];
            float* dst = hbuf + ((u64)(b*64 + o)*512 + n)*64 + tl*8;
#pragma unroll
            for (int j = 0; j < 4; ++j){
                float2 s = unpk(acc[i*4 + j]);
                float2 g = *(const float2*)(gs + o*64 + tl*8 + 2*j);
                float2 h;
                h.x = tanhf(s.x + bia) * g.x;
                h.y = tanhf(s.y + bia) * g.y;
                *(float2*)(dst + 2*j) = h;
            }
        }
    }
}

// ---------------------------------------------------------------------------
// q-gen: per (b,n), stacked [128 rows = W'_{2z},W'_{2z+1}] x h[64 c' x 64 l]
// ---------------------------------------------------------------------------
__global__ __launch_bounds__(256) void k_qgen(){
    __shared__ __align__(16) float As[32*128];
    __shared__ __align__(16) float Bs[32*64];
    int bn = blockIdx.x, z = blockIdx.y;
    int b = bn >> 9, n = bn & 511;
    int tid = threadIdx.x, tv = tid & 31, tl = tid >> 5;
    const float* hb = g_pool + 13ULL*BUFSZ + (u64)b*64*512*64 + (u64)n*64;

    u64 acc[16];
#pragma unroll
    for (int i = 0; i < 16; ++i) acc[i] = 0ULL;

    for (int w0 = 0; w0 < 64; w0 += 32){
#pragma unroll
        for (int i = 0; i < 16; ++i){
            int idx = i*256 + tid;
            int kk = idx >> 7, o = idx & 127;
            int m = 2*z + (o >> 6);
            As[idx] = g_Wq[m*4096 + (w0 + kk)*64 + (o & 63)];
        }
#pragma unroll
        for (int i = 0; i < 8; ++i){
            int idx = i*256 + tid;
            Bs[idx] = hb[(u64)(w0 + (idx >> 6))*32768 + (idx & 63)];
        }
        __syncthreads();
        gemm32(As, Bs, tv, tl, acc);
        __syncthreads();
    }

#pragma unroll
    for (int i = 0; i < 4; ++i){
        int o = tv*4 + i;
        int m = 2*z + (o >> 6), c = o & 63;
        float* dst = g_pool + (u64)m*BUFSZ + ((u64)(b*64 + c)*512 + n)*64 + tl*8;
#pragma unroll
        for (int j = 0; j < 4; ++j)
            *(float2*)(dst + 2*j) = unpk(acc[i*4 + j]);
    }
}

// ---------------------------------------------------------------------------
// node GEMM Horner step: rout = qadd + L rin = qadd - rin + M @ rin
// FINAL: out[..., l+6] = ACC + qadd - rin + M rin + bias   (l < 58)
// ---------------------------------------------------------------------------
template<bool FINAL>
__global__ __launch_bounds__(256)
void k_node(int asel, int rid, int qid, int oid, float* __restrict__ outp){
    __shared__ __align__(16) float As[32*128];
    __shared__ __align__(16) float Bs[32*64];
    const float* A    = asel ? g_AnT : g_An;
    const float* rin  = g_pool + (u64)rid*BUFSZ;
    const float* qadd = g_pool + (u64)qid*BUFSZ;
    float* rout       = g_pool + (u64)oid*BUFSZ;
    const float* accb = g_pool + 12ULL*BUFSZ;

    int bc = blockIdx.x, v0 = blockIdx.y * 128;
    int tid = threadIdx.x, tv = tid & 31, tl = tid >> 5;
    const float* rb = rin + (u64)bc*512*64;

    u64 acc[16];
#pragma unroll
    for (int i = 0; i < 16; ++i) acc[i] = 0ULL;

    for (int w0 = 0; w0 < 512; w0 += 32){
#pragma unroll
        for (int i = 0; i < 16; ++i){
            int idx = i*256 + tid;
            As[idx] = A[(u64)(w0 + (idx >> 7))*512 + v0 + (idx & 127)];
        }
#pragma unroll
        for (int i = 0; i < 8; ++i){
            int idx = i*256 + tid;
            Bs[idx] = rb[(u64)(w0 + (idx >> 6))*64 + (idx & 63)];
        }
        __syncthreads();
        gemm32(As, Bs, tv, tl, acc);
        __syncthreads();
    }

    float bia = FINAL ? g_bias[bc & 63] : 0.f;
#pragma unroll
    for (int i = 0; i < 4; ++i){
        int v = v0 + tv*4 + i;
        u64 rowoff = ((u64)bc*512 + v)*64;
#pragma unroll
        for (int j = 0; j < 4; ++j){
            int l0 = tl*8 + 2*j;
            u64 idx = rowoff + l0;
            float2 a = unpk(acc[i*4 + j]);
            float2 q = *(const float2*)(qadd + idx);
            float2 r = *(const float2*)(rin + idx);
            a.x += q.x - r.x;
            a.y += q.y - r.y;
            if (!FINAL){
                *(float2*)(rout + idx) = a;
            } else if (l0 < 58){
                float2 ac = *(const float2*)(accb + idx);
                a.x += ac.x + bia;
                a.y += ac.y + bia;
                *(float2*)(outp + rowoff + l0 + 6) = a;
            }
        }
    }
}

__global__ void k_zeropad(float* __restrict__ outp){
    int i = blockIdx.x*256 + threadIdx.x;
    if (i < 8*64*512*6){
        int row = i / 6, t = i - row*6;
        outp[(u64)row*64 + t] = 0.f;
    }
}

// ---------------------------------------------------------------------------
extern "C" void kernel_launch(void* const* d_in, const int* in_sizes, int n_in,
                              void* d_out, int out_size){
    (void)in_sizes; (void)n_in; (void)out_size;
    const float* x   = (const float*)d_in[0];
    const float* adj = (const float*)d_in[1];
    float* out = (float*)d_out;

    k_deg <<<512, 256>>>(adj);
    k_norm<<<512, 256>>>(adj);
    k_prep<<<64, 256>>>(
        (const float*)d_in[ 2], (const float*)d_in[ 3], (const float*)d_in[ 4], (const float*)d_in[ 5],
        (const float*)d_in[ 6], (const float*)d_in[ 7], (const float*)d_in[ 8], (const float*)d_in[ 9],
        (const float*)d_in[10], (const float*)d_in[11], (const float*)d_in[12], (const float*)d_in[13],
        (const float*)d_in[14], (const float*)d_in[15], (const float*)d_in[16], (const float*)d_in[17],
        (const float*)d_in[18], (const float*)d_in[19], (const float*)d_in[20], (const float*)d_in[21]);

    k_incept<<<4096, 256>>>(x);
    k_qgen<<<dim3(4096, 5), 256>>>();

    dim3 ng(512, 4);
    // branch 1 (An):  ACC = q0 + L(q1 + L(q2 + L(q3 + L q4)))
    k_node<false><<<ng, 256>>>(0,  4, 3, 10, nullptr);
    k_node<false><<<ng, 256>>>(0, 10, 2, 11, nullptr);
    k_node<false><<<ng, 256>>>(0, 11, 1, 10, nullptr);
    k_node<false><<<ng, 256>>>(0, 10, 0, 12, nullptr);
    // branch 2 (AnT): out = ACC + q5 + L(q6 + L(q7 + L(q8 + L q9))) + bias
    k_node<false><<<ng, 256>>>(1,  9, 8, 10, nullptr);
    k_node<false><<<ng, 256>>>(1, 10, 7, 11, nullptr);
    k_node<false><<<ng, 256>>>(1, 11, 6, 10, nullptr);
    k_node<true ><<<ng, 256>>>(1, 10, 5,  0, out);

    k_zeropad<<<6144, 256>>>(out);
}

// round 6
// speedup vs baseline: 1.5545x; 1.5545x over previous
#include <cuda_runtime.h>
#include <cuda_bf16.h>

typedef unsigned long long u64;
typedef unsigned int u32;

// ---------------------------------------------------------------------------
// Shapes: B=8, C=64, N=512, T=64, valid L=58 (stored padded to 64).
// fp32 pool: q0..q9 (ids 0-9), (10,11 unused), ACC=12, H=13.
// bf16 pool slots (BUFSZ each): 0/1 seed1(q4) hi/lo, 2/3 & 4/5 ping-pong,
//                               6/7 seed2(q9) hi/lo.
// ---------------------------------------------------------------------------
#define BUFSZ (8ULL*64ULL*512ULL*64ULL)

__device__ float g_pool[14ULL*BUFSZ];
__device__ __nv_bfloat16 g_bf[8ULL*BUFSZ];
__device__ __nv_bfloat16 g_Abf[4ULL*512*512];  // [asel*2+hi/lo][v][w] of (M - I)

__device__ float g_An [512*512];   // [w][v] = M1[v][w]
__device__ float g_AnT[512*512];   // [w][v] = M2[v][w]
__device__ float g_rd1[512], g_rd2[512];
__device__ float g_W7[448*128];    // [kd][o]
__device__ float g_b7[128];
__device__ float g_Wq[10*64*64];   // [m][cp][c]
__device__ float g_bias[64];

// ---------------------------------------------------------------------------
// helpers
// ---------------------------------------------------------------------------
__device__ __forceinline__ u32 smem_u32(const void* p){
    u32 a;
    asm("{ .reg .u64 t; cvta.to.shared.u64 t, %1; cvt.u32.u64 %0, t; }" : "=r"(a) : "l"(p));
    return a;
}
__device__ __forceinline__ u64 dup2(float a){
    u64 r; asm("mov.b64 %0, {%1,%1};" : "=l"(r) : "f"(a)); return r;
}
__device__ __forceinline__ void ffma2(u64 &d, u64 a, u64 b){
    asm("fma.rn.f32x2 %0, %1, %2, %0;" : "+l"(d) : "l"(a), "l"(b));
}
__device__ __forceinline__ float2 unpk(u64 u){
    union { u64 u; float2 f; } c; c.u = u; return c.f;
}
// split a pair of fp32 into packed bf16 hi / bf16 lo (hi+lo ~ 17-bit mantissa)
__device__ __forceinline__ void split2(float a0, float a1, u32& hi, u32& lo){
    __nv_bfloat16 h0 = __float2bfloat16(a0);
    __nv_bfloat16 h1 = __float2bfloat16(a1);
    float r0 = a0 - __bfloat162float(h0);
    float r1 = a1 - __bfloat162float(h1);
    union { __nv_bfloat162 v; u32 u; } ch, cl;
    ch.v = __halves2bfloat162(h0, h1);
    cl.v = __halves2bfloat162(__float2bfloat16(r0), __float2bfloat16(r1));
    hi = ch.u; lo = cl.u;
}

// ---------------------------------------------------------------------------
// mma.sync / ldmatrix wrappers (baseline PTX, legal on compute_103)
// ---------------------------------------------------------------------------
__device__ __forceinline__ void mma16816(float* c, const u32* a, u32 b0, u32 b1){
    asm volatile(
        "mma.sync.aligned.m16n8k16.row.col.f32.bf16.bf16.f32 "
        "{%0,%1,%2,%3}, {%4,%5,%6,%7}, {%8,%9}, {%0,%1,%2,%3};"
        : "+f"(c[0]), "+f"(c[1]), "+f"(c[2]), "+f"(c[3])
        : "r"(a[0]), "r"(a[1]), "r"(a[2]), "r"(a[3]), "r"(b0), "r"(b1));
}
__device__ __forceinline__ void ldmA(u32* r, u32 addr){
    asm volatile("ldmatrix.sync.aligned.m8n8.x4.shared.b16 {%0,%1,%2,%3}, [%4];"
        : "=r"(r[0]), "=r"(r[1]), "=r"(r[2]), "=r"(r[3]) : "r"(addr));
}
__device__ __forceinline__ void ldmBT(u32* r, u32 addr){
    asm volatile("ldmatrix.sync.aligned.m8n8.x4.trans.shared.b16 {%0,%1,%2,%3}, [%4];"
        : "=r"(r[0]), "=r"(r[1]), "=r"(r[2]), "=r"(r[3]) : "r"(addr));
}

// ---------------------------------------------------------------------------
// FFMA2 micro-GEMM (incept / qgen)
// ---------------------------------------------------------------------------
__device__ __forceinline__ void gemm32(const float* __restrict__ As,
                                       const float* __restrict__ Bs,
                                       int tv, int tl, u64* acc){
#pragma unroll 8
    for (int kk = 0; kk < 32; ++kk){
        float4 av = *(const float4*)(As + kk*128 + (tv<<2));
        const u64* bp = (const u64*)(Bs + (kk<<6) + (tl<<3));
        u64 a0=dup2(av.x), a1=dup2(av.y), a2=dup2(av.z), a3=dup2(av.w);
        u64 b0=bp[0], b1=bp[1], b2=bp[2], b3=bp[3];
        ffma2(acc[ 0],a0,b0); ffma2(acc[ 1],a0,b1); ffma2(acc[ 2],a0,b2); ffma2(acc[ 3],a0,b3);
        ffma2(acc[ 4],a1,b0); ffma2(acc[ 5],a1,b1); ffma2(acc[ 6],a1,b2); ffma2(acc[ 7],a1,b3);
        ffma2(acc[ 8],a2,b0); ffma2(acc[ 9],a2,b1); ffma2(acc[10],a2,b2); ffma2(acc[11],a2,b3);
        ffma2(acc[12],a3,b0); ffma2(acc[13],a3,b1); ffma2(acc[14],a3,b2); ffma2(acc[15],a3,b3);
    }
}

// ---------------------------------------------------------------------------
// degrees + normalized adjacencies
// ---------------------------------------------------------------------------
__global__ void k_deg(const float* __restrict__ adj){
    int v = blockIdx.x, tid = threadIdx.x;
    float s1 = 0.f, s2 = 0.f;
    for (int w = tid; w < 512; w += 256){
        s1 += adj[v*512 + w];
        s2 += adj[w*512 + v];
    }
    __shared__ float r1[256], r2[256];
    r1[tid] = s1; r2[tid] = s2;
    __syncthreads();
    for (int s = 128; s > 0; s >>= 1){
        if (tid < s){ r1[tid] += r1[tid+s]; r2[tid] += r2[tid+s]; }
        __syncthreads();
    }
    if (tid == 0){
        g_rd1[v] = rsqrtf(r1[0] + 1.f);
        g_rd2[v] = rsqrtf(r2[0] + 1.f);
    }
}

__global__ void k_norm(const float* __restrict__ adj){
    int w = blockIdx.x;
    float dw1 = g_rd1[w], dw2 = g_rd2[w];
    for (int v = threadIdx.x; v < 512; v += 256){
        float e = (v == w) ? 1.f : 0.f;
        g_An [w*512 + v] = g_rd1[v] * (adj[v*512 + w] + e) * dw1;
        g_AnT[w*512 + v] = g_rd2[v] * (adj[w*512 + v] + e) * dw2;
    }
}

// split (An - I)/(AnT - I) into bf16 hi/lo in [v][w] (K-major) layout
__global__ void k_prepA(){
    int v = blockIdx.x;
    for (int w = threadIdx.x; w < 512; w += 256){
        float e = (v == w) ? 1.f : 0.f;
        float a1 = g_An [w*512 + v] - e;
        float a2 = g_AnT[w*512 + v] - e;
        __nv_bfloat16 h1 = __float2bfloat16(a1);
        __nv_bfloat16 l1 = __float2bfloat16(a1 - __bfloat162float(h1));
        __nv_bfloat16 h2 = __float2bfloat16(a2);
        __nv_bfloat16 l2 = __float2bfloat16(a2 - __bfloat162float(h2));
        g_Abf[0ULL*262144 + v*512 + w] = h1;
        g_Abf[1ULL*262144 + v*512 + w] = l1;
        g_Abf[2ULL*262144 + v*512 + w] = h2;
        g_Abf[3ULL*262144 + v*512 + w] = l2;
    }
}

// ---------------------------------------------------------------------------
// prep: pad inception weights to k=7, build Horner W'_j
// ---------------------------------------------------------------------------
__global__ void k_prep(const float* i1w0,const float* i1b0,const float* i1w1,const float* i1b1,
                       const float* i1w2,const float* i1b2,const float* i1w3,const float* i1b3,
                       const float* i2w0,const float* i2b0,const float* i2w1,const float* i2b1,
                       const float* i2w2,const float* i2b2,const float* i2w3,const float* i2b3,
                       const float* m1w,const float* m1b,const float* m2w,const float* m2b){
    int g0 = blockIdx.x*256 + threadIdx.x, gstr = gridDim.x*256;
    const float* WS[8] = {i1w0,i1w1,i1w2,i1w3,i2w0,i2w1,i2w2,i2w3};
    const float* BS[8] = {i1b0,i1b1,i1b2,i1b3,i2b0,i2b1,i2b2,i2b3};
    const int KERN[4] = {2,3,6,7};

    for (int idx = g0; idx < 448*128; idx += gstr){
        int kd = idx >> 7, o = idx & 127;
        int c = kd / 7, tau = kd - c*7;
        int br = o >> 6, j = (o >> 4) & 3, oc = o & 15;
        int k = KERN[j];
        int t = tau - (7 - k);
        g_W7[idx] = (t >= 0) ? WS[br*4 + j][(oc*64 + c)*k + t] : 0.f;
    }
    for (int idx = g0; idx < 128; idx += gstr){
        int br = idx >> 6, j = (idx >> 4) & 3, oc = idx & 15;
        g_b7[idx] = BS[br*4 + j][oc];
    }
    for (int idx = g0; idx < 64; idx += gstr)
        g_bias[idx] = m1b[idx] + m2b[idx];

    const float COEF[5][5] = {
        {1.f, 1.f,      1.f,      1.f,      1.f     },
        {0.f, 1.f/3.f,  2.f/3.f,  1.f,      1.f     },
        {0.f, 0.f,      1.f/3.f,  1.f/3.f,  0.5f    },
        {0.f, 0.f,      0.f,      1.f/3.f,  1.f/6.f },
        {0.f, 0.f,      0.f,      0.f,      1.f/24.f}};
    for (int idx = g0; idx < 10*4096; idx += gstr){
        int m = idx >> 12, cp = (idx >> 6) & 63, c = idx & 63;
        int j = m % 5;
        const float* mw = (m < 5) ? m1w : m2w;
        float s = 0.f;
#pragma unroll
        for (int g = 0; g < 5; ++g)
            s += COEF[j][g] * mw[c*320 + g*64 + cp];
        g_Wq[idx] = s;
    }
}

// ---------------------------------------------------------------------------
// inception: per (b,n) GEMM [128 o x 448] x [448 x 64 l] with fused gate
// ---------------------------------------------------------------------------
__global__ __launch_bounds__(256) void k_incept(const float* __restrict__ x){
    __shared__ __align__(16) float As[32*128];
    __shared__ __align__(16) float Bs[32*64];
    int bn = blockIdx.x;
    int b = bn >> 9, n = bn & 511;
    int tid = threadIdx.x, tv = tid & 31, tl = tid >> 5;
    const float* xb = x + (u64)b*64*512*64 + (u64)n*64;

    u64 acc[16];
#pragma unroll
    for (int i = 0; i < 16; ++i) acc[i] = 0ULL;

    for (int w0 = 0; w0 < 448; w0 += 32){
#pragma unroll
        for (int i = 0; i < 16; ++i){
            int idx = i*256 + tid;
            As[idx] = g_W7[w0*128 + idx];
        }
#pragma unroll
        for (int i = 0; i < 8; ++i){
            int idx = i*256 + tid;
            int kd = w0 + (idx >> 6), l = idx & 63;
            int c = kd / 7, tau = kd - c*7;
            int t = l + tau;
            Bs[idx] = (t < 64) ? xb[(u64)c*32768 + t] : 0.f;
        }
        __syncthreads();
        gemm32(As, Bs, tv, tl, acc);
        __syncthreads();
    }

    float* gs = As;
    if (tv >= 16){
#pragma unroll
        for (int i = 0; i < 4; ++i){
            int o = tv*4 + i;
            int gc = o - 64;
            float bia = g_b7[o];
#pragma unroll
            for (int j = 0; j < 4; ++j){
                float2 s = unpk(acc[i*4 + j]);
                float2 g;
                g.x = 1.f/(1.f + expf(-(s.x + bia)));
                g.y = 1.f/(1.f + expf(-(s.y + bia)));
                *(float2*)(gs + gc*64 + tl*8 + 2*j) = g;
            }
        }
    }
    __syncthreads();
    if (tv < 16){
        float* hbuf = g_pool + 13ULL*BUFSZ;
#pragma unroll
        for (int i = 0; i < 4; ++i){
            int o = tv*4 + i;
            float bia = g_b7[o];
            float* dst = hbuf + ((u64)(b*64 + o)*512 + n)*64 + tl*8;
#pragma unroll
            for (int j = 0; j < 4; ++j){
                float2 s = unpk(acc[i*4 + j]);
                float2 g = *(const float2*)(gs + o*64 + tl*8 + 2*j);
                float2 h;
                h.x = tanhf(s.x + bia) * g.x;
                h.y = tanhf(s.y + bia) * g.y;
                *(float2*)(dst + 2*j) = h;
            }
        }
    }
}

// ---------------------------------------------------------------------------
// q-gen: per (b,n), stacked [128 rows = W'_{2z},W'_{2z+1}] x h[64 c' x 64 l]
// q4/q9 (Horner seeds) are emitted directly as bf16 hi/lo (slots 0/1, 6/7).
// ---------------------------------------------------------------------------
__global__ __launch_bounds__(256) void k_qgen(){
    __shared__ __align__(16) float As[32*128];
    __shared__ __align__(16) float Bs[32*64];
    int bn = blockIdx.x, z = blockIdx.y;
    int b = bn >> 9, n = bn & 511;
    int tid = threadIdx.x, tv = tid & 31, tl = tid >> 5;
    const float* hb = g_pool + 13ULL*BUFSZ + (u64)b*64*512*64 + (u64)n*64;

    u64 acc[16];
#pragma unroll
    for (int i = 0; i < 16; ++i) acc[i] = 0ULL;

    for (int w0 = 0; w0 < 64; w0 += 32){
#pragma unroll
        for (int i = 0; i < 16; ++i){
            int idx = i*256 + tid;
            int kk = idx >> 7, o = idx & 127;
            int m = 2*z + (o >> 6);
            As[idx] = g_Wq[m*4096 + (w0 + kk)*64 + (o & 63)];
        }
#pragma unroll
        for (int i = 0; i < 8; ++i){
            int idx = i*256 + tid;
            Bs[idx] = hb[(u64)(w0 + (idx >> 6))*32768 + (idx & 63)];
        }
        __syncthreads();
        gemm32(As, Bs, tv, tl, acc);
        __syncthreads();
    }

#pragma unroll
    for (int i = 0; i < 4; ++i){
        int o = tv*4 + i;
        int m = 2*z + (o >> 6), c = o & 63;
        u64 eoff = ((u64)(b*64 + c)*512 + n)*64 + tl*8;
        if (m == 4 || m == 9){
            __nv_bfloat16* wh = g_bf + (u64)(m == 4 ? 0 : 6)*BUFSZ + eoff;
            __nv_bfloat16* wl = wh + BUFSZ;
#pragma unroll
            for (int j = 0; j < 4; ++j){
                float2 a = unpk(acc[i*4 + j]);
                u32 h, lo; split2(a.x, a.y, h, lo);
                *(u32*)(wh + 2*j) = h;
                *(u32*)(wl + 2*j) = lo;
            }
        } else {
            float* dst = g_pool + (u64)m*BUFSZ + eoff;
#pragma unroll
            for (int j = 0; j < 4; ++j)
                *(float2*)(dst + 2*j) = unpk(acc[i*4 + j]);
        }
    }
}

// ---------------------------------------------------------------------------
// tensor-core (mma.sync) Horner node step: r' = q + (M - I) @ r
// M-I via split-bf16 (hi+lo), 3 MMA products (hh, hl, lh) into fp32 acc.
// MODE 0: write r' as bf16 hi/lo (slots wslot, wslot+1)
// MODE 1: write r' as fp32 into ACC (buffer 12)
// MODE 2: out[..., l+6] = ACC + r' + bias  (l < 58)
// CTA: 128 threads = 4 warps; tile 128v x 64l; warp tile 32v x 64l.
// ---------------------------------------------------------------------------
template<int MODE>
__global__ __launch_bounds__(128)
void k_node_mma(int asel, int qid, int bslot, int wslot, float* __restrict__ outp){
    __shared__ __align__(16) __nv_bfloat16 sAh[128*40];   // 80B rows (pad: conflict-free)
    __shared__ __align__(16) __nv_bfloat16 sAl[128*40];
    __shared__ __align__(16) __nv_bfloat16 sBh[32*72];    // 144B rows
    __shared__ __align__(16) __nv_bfloat16 sBl[32*72];

    int tid = threadIdx.x, lane = tid & 31, wid = tid >> 5;
    int bc = blockIdx.x, v0c = blockIdx.y << 7;

    const __nv_bfloat16* Ah = g_Abf + (u64)(asel*2)*262144;
    const __nv_bfloat16* Al = Ah + 262144;
    const __nv_bfloat16* Bh = g_bf + (u64)bslot*BUFSZ + (u64)bc*32768;
    const __nv_bfloat16* Bl = Bh + BUFSZ;

    u32 uAh = smem_u32(sAh), uAl = smem_u32(sAl);
    u32 uBh = smem_u32(sBh), uBl = smem_u32(sBl);

    float acc[2][8][4];
#pragma unroll
    for (int m = 0; m < 2; ++m)
#pragma unroll
        for (int j = 0; j < 8; ++j)
#pragma unroll
            for (int e = 0; e < 4; ++e) acc[m][j][e] = 0.f;

    for (int kc = 0; kc < 16; ++kc){
        int w0 = kc*32;
        // A chunk: 128 rows x 32k bf16 (hi+lo), 16B segments
#pragma unroll
        for (int i = 0; i < 4; ++i){
            int idx = i*128 + tid;
            int row = idx >> 2, seg = idx & 3;
            u64 goff = (u64)(v0c + row)*512 + w0 + seg*8;
            *(uint4*)(sAh + row*40 + seg*8) = *(const uint4*)(Ah + goff);
            *(uint4*)(sAl + row*40 + seg*8) = *(const uint4*)(Al + goff);
        }
        // B chunk: 32 rows(k=w) x 64n(l) bf16 (hi+lo)
#pragma unroll
        for (int i = 0; i < 2; ++i){
            int idx = i*128 + tid;
            int row = idx >> 3, seg = idx & 7;
            u64 goff = (u64)(w0 + row)*64 + seg*8;
            *(uint4*)(sBh + row*72 + seg*8) = *(const uint4*)(Bh + goff);
            *(uint4*)(sBl + row*72 + seg*8) = *(const uint4*)(Bl + goff);
        }
        __syncthreads();
#pragma unroll
        for (int ks = 0; ks < 32; ks += 16){
            u32 ah[2][4], al[2][4];
            int arow = lane & 15, acol = ks + (lane >> 4)*8;
#pragma unroll
            for (int m = 0; m < 2; ++m){
                u32 ao = (u32)((wid*32 + m*16 + arow)*40 + acol)*2;
                ldmA(ah[m], uAh + ao);
                ldmA(al[m], uAl + ao);
            }
            int brow = ks + (lane & 15), bcol = (lane >> 4)*8;
#pragma unroll
            for (int g = 0; g < 4; ++g){
                u32 bh[4], bl[4];
                u32 bo = (u32)(brow*72 + g*16 + bcol)*2;
                ldmBT(bh, uBh + bo);
                ldmBT(bl, uBl + bo);
#pragma unroll
                for (int m = 0; m < 2; ++m){
#pragma unroll
                    for (int h = 0; h < 2; ++h){
                        float* c = acc[m][g*2 + h];
                        mma16816(c, ah[m], bh[2*h], bh[2*h+1]);
                        mma16816(c, ah[m], bl[2*h], bl[2*h+1]);
                        mma16816(c, al[m], bh[2*h], bh[2*h+1]);
                    }
                }
            }
        }
        __syncthreads();
    }

    // epilogue: acc[m][jj]: rows v, v+8 (c0c1 / c2c3), cols l, l+1
    const float* qp = g_pool + (u64)qid*BUFSZ + (u64)bc*32768;
    int lbase = (lane & 3)*2, rbase = lane >> 2;
#pragma unroll
    for (int m = 0; m < 2; ++m){
        int v = v0c + wid*32 + m*16 + rbase;
#pragma unroll
        for (int jj = 0; jj < 8; ++jj){
            int l = jj*8 + lbase;
            float* c = acc[m][jj];
            float2 q0 = *(const float2*)(qp + (u64)v*64 + l);
            float2 q1 = *(const float2*)(qp + (u64)(v+8)*64 + l);
            float a0 = c[0] + q0.x, a1 = c[1] + q0.y;
            float a2 = c[2] + q1.x, a3 = c[3] + q1.y;
            if (MODE == 0){
                __nv_bfloat16* wh = g_bf + (u64)wslot*BUFSZ + (u64)bc*32768;
                __nv_bfloat16* wl = wh + BUFSZ;
                u32 h0, l0, h1, l1;
                split2(a0, a1, h0, l0);
                split2(a2, a3, h1, l1);
                *(u32*)(wh + (u64)v*64 + l) = h0;
                *(u32*)(wl + (u64)v*64 + l) = l0;
                *(u32*)(wh + (u64)(v+8)*64 + l) = h1;
                *(u32*)(wl + (u64)(v+8)*64 + l) = l1;
            } else if (MODE == 1){
                float* op = g_pool + 12ULL*BUFSZ + (u64)bc*32768;
                *(float2*)(op + (u64)v*64 + l) = make_float2(a0, a1);
                *(float2*)(op + (u64)(v+8)*64 + l) = make_float2(a2, a3);
            } else {
                const float* ap = g_pool + 12ULL*BUFSZ + (u64)bc*32768;
                float bia = g_bias[bc & 63];
                float* op = outp + (u64)bc*32768;
                a0 += ap[(u64)v*64 + l] + bia;
                a1 += ap[(u64)v*64 + l + 1] + bia;
                a2 += ap[(u64)(v+8)*64 + l] + bia;
                a3 += ap[(u64)(v+8)*64 + l + 1] + bia;
                if (l < 58)     op[(u64)v*64 + l + 6]       = a0;
                if (l + 1 < 58) op[(u64)v*64 + l + 7]       = a1;
                if (l < 58)     op[(u64)(v+8)*64 + l + 6]   = a2;
                if (l + 1 < 58) op[(u64)(v+8)*64 + l + 7]   = a3;
            }
        }
    }
}

__global__ void k_zeropad(float* __restrict__ outp){
    int i = blockIdx.x*256 + threadIdx.x;
    if (i < 8*64*512*6){
        int row = i / 6, t = i - row*6;
        outp[(u64)row*64 + t] = 0.f;
    }
}

// ---------------------------------------------------------------------------
extern "C" void kernel_launch(void* const* d_in, const int* in_sizes, int n_in,
                              void* d_out, int out_size){
    (void)in_sizes; (void)n_in; (void)out_size;
    const float* x   = (const float*)d_in[0];
    const float* adj = (const float*)d_in[1];
    float* out = (float*)d_out;

    k_deg  <<<512, 256>>>(adj);
    k_norm <<<512, 256>>>(adj);
    k_prepA<<<512, 256>>>();
    k_prep<<<64, 256>>>(
        (const float*)d_in[ 2], (const float*)d_in[ 3], (const float*)d_in[ 4], (const float*)d_in[ 5],
        (const float*)d_in[ 6], (const float*)d_in[ 7], (const float*)d_in[ 8], (const float*)d_in[ 9],
        (const float*)d_in[10], (const float*)d_in[11], (const float*)d_in[12], (const float*)d_in[13],
        (const float*)d_in[14], (const float*)d_in[15], (const float*)d_in[16], (const float*)d_in[17],
        (const float*)d_in[18], (const float*)d_in[19], (const float*)d_in[20], (const float*)d_in[21]);

    k_incept<<<4096, 256>>>(x);
    k_qgen<<<dim3(4096, 5), 256>>>();

    dim3 ng(512, 4);
    // branch 1 (An):  ACC = q0 + L(q1 + L(q2 + L(q3 + L q4)))
    k_node_mma<0><<<ng, 128>>>(0, 3, 0, 2, nullptr);
    k_node_mma<0><<<ng, 128>>>(0, 2, 2, 4, nullptr);
    k_node_mma<0><<<ng, 128>>>(0, 1, 4, 2, nullptr);
    k_node_mma<1><<<ng, 128>>>(0, 0, 2, 0, nullptr);
    // branch 2 (AnT): out = ACC + q5 + L(q6 + L(q7 + L(q8 + L q9))) + bias
    k_node_mma<0><<<ng, 128>>>(1, 8, 6, 2, nullptr);
    k_node_mma<0><<<ng, 128>>>(1, 7, 2, 4, nullptr);
    k_node_mma<0><<<ng, 128>>>(1, 6, 4, 2, nullptr);
    k_node_mma<2><<<ng, 128>>>(1, 5, 2, 0, out);

    k_zeropad<<<6144, 256>>>(out);
}

// round 8
// speedup vs baseline: 2.1478x; 1.3816x over previous
#include <cuda_runtime.h>
#include <cuda_bf16.h>

typedef unsigned long long u64;
typedef unsigned int u32;

// ---------------------------------------------------------------------------
// Shapes: B=8, C=64, N=512, T=64, valid L=58 (stored padded to 64).
// fp32 pool: q0..q9 (ids 0-9; 4 and 9 unused as fp32), ACC=12.
// bf16 pool slots (BUFSZ each):
//   0/1 seed1(q4) hi/lo, 2/3 & 4/5 branch0 ping-pong,
//   6/7 seed2(q9) hi/lo, 8/9 & 10/11 branch1 ping-pong.
// ---------------------------------------------------------------------------
#define BUFSZ (8ULL*64ULL*512ULL*64ULL)

__device__ float g_pool[13ULL*BUFSZ];
__device__ __nv_bfloat16 g_bf[12ULL*BUFSZ];
__device__ __nv_bfloat16 g_Abf[4ULL*512*512];  // [asel*2+hi/lo][v][w] of (M - I)

__device__ float g_An [512*512];   // [w][v] = M1[v][w]
__device__ float g_AnT[512*512];   // [w][v] = M2[v][w]
__device__ float g_rd1[512], g_rd2[512];
__device__ __nv_bfloat16 g_W7h[128*448];   // [o][kd] hi
__device__ __nv_bfloat16 g_W7l[128*448];   // [o][kd] lo
__device__ float g_b7[128];
__device__ __nv_bfloat16 g_Wqh[10*64*64];  // [m][out][in] hi  (MMA A-row = out)
__device__ __nv_bfloat16 g_Wql[10*64*64];  // [m][out][in] lo
__device__ float g_bias[64];

// ---------------------------------------------------------------------------
// helpers
// ---------------------------------------------------------------------------
__device__ __forceinline__ u32 smem_u32(const void* p){
    u32 a;
    asm("{ .reg .u64 t; cvta.to.shared.u64 t, %1; cvt.u32.u64 %0, t; }" : "=r"(a) : "l"(p));
    return a;
}
// split a pair of fp32 into packed bf16 hi / bf16 lo
__device__ __forceinline__ void split2(float a0, float a1, u32& hi, u32& lo){
    __nv_bfloat16 h0 = __float2bfloat16(a0);
    __nv_bfloat16 h1 = __float2bfloat16(a1);
    float r0 = a0 - __bfloat162float(h0);
    float r1 = a1 - __bfloat162float(h1);
    union { __nv_bfloat162 v; u32 u; } ch, cl;
    ch.v = __halves2bfloat162(h0, h1);
    cl.v = __halves2bfloat162(__float2bfloat16(r0), __float2bfloat16(r1));
    hi = ch.u; lo = cl.u;
}

// ---------------------------------------------------------------------------
// mma.sync / ldmatrix wrappers (baseline PTX, legal on compute_103)
// ---------------------------------------------------------------------------
__device__ __forceinline__ void mma16816(float* c, const u32* a, u32 b0, u32 b1){
    asm volatile(
        "mma.sync.aligned.m16n8k16.row.col.f32.bf16.bf16.f32 "
        "{%0,%1,%2,%3}, {%4,%5,%6,%7}, {%8,%9}, {%0,%1,%2,%3};"
        : "+f"(c[0]), "+f"(c[1]), "+f"(c[2]), "+f"(c[3])
        : "r"(a[0]), "r"(a[1]), "r"(a[2]), "r"(a[3]), "r"(b0), "r"(b1));
}
__device__ __forceinline__ void ldmA(u32* r, u32 addr){
    asm volatile("ldmatrix.sync.aligned.m8n8.x4.shared.b16 {%0,%1,%2,%3}, [%4];"
        : "=r"(r[0]), "=r"(r[1]), "=r"(r[2]), "=r"(r[3]) : "r"(addr));
}
__device__ __forceinline__ void ldmBT(u32* r, u32 addr){
    asm volatile("ldmatrix.sync.aligned.m8n8.x4.trans.shared.b16 {%0,%1,%2,%3}, [%4];"
        : "=r"(r[0]), "=r"(r[1]), "=r"(r[2]), "=r"(r[3]) : "r"(addr));
}

// ---------------------------------------------------------------------------
// degrees + normalized adjacencies
// ---------------------------------------------------------------------------
__global__ void k_deg(const float* __restrict__ adj){
    int v = blockIdx.x, tid = threadIdx.x;
    float s1 = 0.f, s2 = 0.f;
    for (int w = tid; w < 512; w += 256){
        s1 += adj[v*512 + w];
        s2 += adj[w*512 + v];
    }
    __shared__ float r1[256], r2[256];
    r1[tid] = s1; r2[tid] = s2;
    __syncthreads();
    for (int s = 128; s > 0; s >>= 1){
        if (tid < s){ r1[tid] += r1[tid+s]; r2[tid] += r2[tid+s]; }
        __syncthreads();
    }
    if (tid == 0){
        g_rd1[v] = rsqrtf(r1[0] + 1.f);
        g_rd2[v] = rsqrtf(r2[0] + 1.f);
    }
}

__global__ void k_norm(const float* __restrict__ adj){
    int w = blockIdx.x;
    float dw1 = g_rd1[w], dw2 = g_rd2[w];
    for (int v = threadIdx.x; v < 512; v += 256){
        float e = (v == w) ? 1.f : 0.f;
        g_An [w*512 + v] = g_rd1[v] * (adj[v*512 + w] + e) * dw1;
        g_AnT[w*512 + v] = g_rd2[v] * (adj[w*512 + v] + e) * dw2;
    }
}

// split (An - I)/(AnT - I) into bf16 hi/lo in [v][w] (K-major) layout
__global__ void k_prepA(){
    int v = blockIdx.x;
    for (int w = threadIdx.x; w < 512; w += 256){
        float e = (v == w) ? 1.f : 0.f;
        float a1 = g_An [w*512 + v] - e;
        float a2 = g_AnT[w*512 + v] - e;
        __nv_bfloat16 h1 = __float2bfloat16(a1);
        __nv_bfloat16 l1 = __float2bfloat16(a1 - __bfloat162float(h1));
        __nv_bfloat16 h2 = __float2bfloat16(a2);
        __nv_bfloat16 l2 = __float2bfloat16(a2 - __bfloat162float(h2));
        g_Abf[0ULL*262144 + v*512 + w] = h1;
        g_Abf[1ULL*262144 + v*512 + w] = l1;
        g_Abf[2ULL*262144 + v*512 + w] = h2;
        g_Abf[3ULL*262144 + v*512 + w] = l2;
    }
}

// ---------------------------------------------------------------------------
// prep: pad inception weights to k=7 (windows end at l+6), build Horner W'_j,
// split everything to bf16 hi/lo in MMA-friendly layouts.
// ---------------------------------------------------------------------------
__global__ void k_prep(const float* i1w0,const float* i1b0,const float* i1w1,const float* i1b1,
                       const float* i1w2,const float* i1b2,const float* i1w3,const float* i1b3,
                       const float* i2w0,const float* i2b0,const float* i2w1,const float* i2b1,
                       const float* i2w2,const float* i2b2,const float* i2w3,const float* i2b3,
                       const float* m1w,const float* m1b,const float* m2w,const float* m2b){
    int g0 = blockIdx.x*256 + threadIdx.x, gstr = gridDim.x*256;
    const float* WS[8] = {i1w0,i1w1,i1w2,i1w3,i2w0,i2w1,i2w2,i2w3};
    const float* BS[8] = {i1b0,i1b1,i1b2,i1b3,i2b0,i2b1,i2b2,i2b3};
    const int KERN[4] = {2,3,6,7};

    // W7: [o][kd], kd = c*7 + tau
    for (int idx = g0; idx < 128*448; idx += gstr){
        int o = idx / 448, kd = idx - o*448;
        int c = kd / 7, tau = kd - c*7;
        int br = o >> 6, j = (o >> 4) & 3, oc = o & 15;
        int k = KERN[j];
        int t = tau - (7 - k);
        float v = (t >= 0) ? WS[br*4 + j][(oc*64 + c)*k + t] : 0.f;
        __nv_bfloat16 h = __float2bfloat16(v);
        g_W7h[idx] = h;
        g_W7l[idx] = __float2bfloat16(v - __bfloat162float(h));
    }
    for (int idx = g0; idx < 128; idx += gstr){
        int br = idx >> 6, j = (idx >> 4) & 3, oc = idx & 15;
        g_b7[idx] = BS[br*4 + j][oc];
    }
    for (int idx = g0; idx < 64; idx += gstr)
        g_bias[idx] = m1b[idx] + m2b[idx];

    const float COEF[5][5] = {
        {1.f, 1.f,      1.f,      1.f,      1.f     },
        {0.f, 1.f/3.f,  2.f/3.f,  1.f,      1.f     },
        {0.f, 0.f,      1.f/3.f,  1.f/3.f,  0.5f    },
        {0.f, 0.f,      0.f,      1.f/3.f,  1.f/6.f },
        {0.f, 0.f,      0.f,      0.f,      1.f/24.f}};
    // Wq bf16 stored [m][out=c][in=cp] so MMA A-fragment rows are outputs.
    for (int idx = g0; idx < 10*4096; idx += gstr){
        int m = idx >> 12, cp = (idx >> 6) & 63, c = idx & 63;
        int j = m % 5;
        const float* mw = (m < 5) ? m1w : m2w;
        float s = 0.f;
#pragma unroll
        for (int g = 0; g < 5; ++g)
            s += COEF[j][g] * mw[c*320 + g*64 + cp];
        __nv_bfloat16 h = __float2bfloat16(s);
        int widx = (m << 12) + (c << 6) + cp;   // [m][out][in]
        g_Wqh[widx] = h;
        g_Wql[widx] = __float2bfloat16(s - __bfloat162float(h));
    }
}

// ---------------------------------------------------------------------------
// FUSED inception + gate + qgen, all tensor-core (mma.sync split-bf16).
// Per CTA (b,n), 128 threads = 4 warps.
// Stage 1: s[128 o][64 l] = W7[128x448] @ im2col(x)[448x64]; tile M=128,N=64.
// Gate: h[c][l] = tanh(s[c]+b) * sigmoid(s[c+64]+b), split to bf16 hi/lo smem.
// Stage 2: for m=0..9: q_m[64 cp][64 l] = W'_m[64x64] @ h[64x64].
//   m==4 / m==9 written as bf16 hi/lo Horner seeds (slots 0/1, 6/7),
//   others written fp32 to g_pool[m].
// ---------------------------------------------------------------------------
__global__ __launch_bounds__(128) void k_fused(const float* __restrict__ x){
    __shared__ __align__(16) char sm[38912];
    // stage-1 overlays
    __nv_bfloat16* sAh = (__nv_bfloat16*)(sm);            // [128][40]
    __nv_bfloat16* sAl = (__nv_bfloat16*)(sm + 10240);    // [128][40]
    __nv_bfloat16* sBh = (__nv_bfloat16*)(sm + 20480);    // [32][72]
    __nv_bfloat16* sBl = (__nv_bfloat16*)(sm + 25088);    // [32][72]
    // gate / stage-2 overlays
    float*         sG  = (float*)(sm);                    // [64][72] fp32
    __nv_bfloat16* sWh = (__nv_bfloat16*)(sm);            // [64][72]
    __nv_bfloat16* sWl = (__nv_bfloat16*)(sm + 9216);     // [64][72]
    __nv_bfloat16* sHh = (__nv_bfloat16*)(sm + 20480);    // [64][72]
    __nv_bfloat16* sHl = (__nv_bfloat16*)(sm + 29696);    // [64][72]

    int bn = blockIdx.x;
    int b = bn >> 9, n = bn & 511;
    int tid = threadIdx.x, lane = tid & 31, wid = tid >> 5;
    const float* xb = x + (u64)b*64*32768 + (u64)n*64;   // channel stride 512*64

    u32 uAh = smem_u32(sAh), uAl = smem_u32(sAl);
    u32 uBh = smem_u32(sBh), uBl = smem_u32(sBl);
    u32 uWh = smem_u32(sWh), uWl = smem_u32(sWl);
    u32 uHh = smem_u32(sHh), uHl = smem_u32(sHl);

    float acc[2][8][4];
#pragma unroll
    for (int m = 0; m < 2; ++m)
#pragma unroll
        for (int j = 0; j < 8; ++j)
#pragma unroll
            for (int e = 0; e < 4; ++e) acc[m][j][e] = 0.f;

    // ---------------- stage 1: inception GEMM (K = 448, 14 chunks of 32) ----
    for (int kc = 0; kc < 14; ++kc){
        int w0 = kc*32;
#pragma unroll
        for (int i = 0; i < 4; ++i){
            int idx = i*128 + tid;
            int row = idx >> 2, seg = idx & 3;
            *(uint4*)(sAh + row*40 + seg*8) = *(const uint4*)(g_W7h + row*448 + w0 + seg*8);
            *(uint4*)(sAl + row*40 + seg*8) = *(const uint4*)(g_W7l + row*448 + w0 + seg*8);
        }
        // B: im2col rows kd = w0+row, split fp32 -> bf16 hi/lo
#pragma unroll
        for (int i = 0; i < 8; ++i){
            int idx = i*128 + tid;          // (row, lpair): 32 x 32
            int row = idx >> 5, lp = idx & 31, l = lp*2;
            int kd = w0 + row;
            int c = kd / 7, tau = kd - c*7;
            int t = l + tau;
            float v0 = (t < 64) ? xb[(u64)c*32768 + t] : 0.f;
            float v1 = (t + 1 < 64) ? xb[(u64)c*32768 + t + 1] : 0.f;
            u32 h, lo; split2(v0, v1, h, lo);
            *(u32*)(sBh + row*72 + l) = h;
            *(u32*)(sBl + row*72 + l) = lo;
        }
        __syncthreads();
#pragma unroll
        for (int ks = 0; ks < 32; ks += 16){
            u32 ah[2][4], al[2][4];
            int arow = lane & 15, acol = ks + (lane >> 4)*8;
#pragma unroll
            for (int m = 0; m < 2; ++m){
                u32 ao = (u32)((wid*32 + m*16 + arow)*40 + acol)*2;
                ldmA(ah[m], uAh + ao);
                ldmA(al[m], uAl + ao);
            }
            int brow = ks + (lane & 15), bcol = (lane >> 4)*8;
#pragma unroll
            for (int g = 0; g < 4; ++g){
                u32 bh[4], bl[4];
                u32 bo = (u32)(brow*72 + g*16 + bcol)*2;
                ldmBT(bh, uBh + bo);
                ldmBT(bl, uBl + bo);
#pragma unroll
                for (int m = 0; m < 2; ++m){
#pragma unroll
                    for (int h = 0; h < 2; ++h){
                        float* c = acc[m][g*2 + h];
                        mma16816(c, ah[m], bh[2*h], bh[2*h+1]);
                        mma16816(c, ah[m], bl[2*h], bl[2*h+1]);
                        mma16816(c, al[m], bh[2*h], bh[2*h+1]);
                    }
                }
            }
        }
        __syncthreads();
    }

    // ---------------- gate: h = tanh(filt) * sigmoid(gate) ------------------
    int lbase = (lane & 3)*2, rbase = lane >> 2;
    if (wid >= 2){   // gate rows: o = 64..127 -> write sigmoid to sG
#pragma unroll
        for (int m = 0; m < 2; ++m){
            int o = wid*32 + m*16 + rbase;
#pragma unroll
            for (int jj = 0; jj < 8; ++jj){
                int l = jj*8 + lbase;
                float* c = acc[m][jj];
                float b0 = g_b7[o], b1 = g_b7[o + 8];
                float2 g0, g1;
                g0.x = 1.f/(1.f + expf(-(c[0] + b0)));
                g0.y = 1.f/(1.f + expf(-(c[1] + b0)));
                g1.x = 1.f/(1.f + expf(-(c[2] + b1)));
                g1.y = 1.f/(1.f + expf(-(c[3] + b1)));
                *(float2*)(sG + (o - 64)*72 + l) = g0;
                *(float2*)(sG + (o - 64 + 8)*72 + l) = g1;
            }
        }
    }
    __syncthreads();
    if (wid < 2){    // filt rows: o = c = 0..63 -> h split to sHh/sHl
#pragma unroll
        for (int m = 0; m < 2; ++m){
            int c0 = wid*32 + m*16 + rbase;
#pragma unroll
            for (int jj = 0; jj < 8; ++jj){
                int l = jj*8 + lbase;
                float* c = acc[m][jj];
                float b0 = g_b7[c0], b1 = g_b7[c0 + 8];
                float2 ga = *(const float2*)(sG + c0*72 + l);
                float2 gb = *(const float2*)(sG + (c0 + 8)*72 + l);
                float h0 = tanhf(c[0] + b0) * ga.x;
                float h1 = tanhf(c[1] + b0) * ga.y;
                float h2 = tanhf(c[2] + b1) * gb.x;
                float h3 = tanhf(c[3] + b1) * gb.y;
                u32 ph0, pl0, ph1, pl1;
                split2(h0, h1, ph0, pl0);
                split2(h2, h3, ph1, pl1);
                *(u32*)(sHh + c0*72 + l) = ph0;
                *(u32*)(sHl + c0*72 + l) = pl0;
                *(u32*)(sHh + (c0 + 8)*72 + l) = ph1;
                *(u32*)(sHl + (c0 + 8)*72 + l) = pl1;
            }
        }
    }

    // ---------------- stage 2: q_m = W'_m @ h, m = 0..9 ---------------------
    for (int m = 0; m < 10; ++m){
        __syncthreads();   // sH visible (first iter); sW safe to overwrite
#pragma unroll
        for (int i = 0; i < 4; ++i){
            int idx = i*128 + tid;
            int row = idx >> 3, seg = idx & 7;
            *(uint4*)(sWh + row*72 + seg*8) = *(const uint4*)(g_Wqh + m*4096 + row*64 + seg*8);
            *(uint4*)(sWl + row*72 + seg*8) = *(const uint4*)(g_Wql + m*4096 + row*64 + seg*8);
        }
        __syncthreads();

        float a2[8][4];
#pragma unroll
        for (int j = 0; j < 8; ++j)
#pragma unroll
            for (int e = 0; e < 4; ++e) a2[j][e] = 0.f;

#pragma unroll
        for (int ks = 0; ks < 64; ks += 16){
            u32 ah[4], al[4];
            u32 ao = (u32)((wid*16 + (lane & 15))*72 + ks + (lane >> 4)*8)*2;
            ldmA(ah, uWh + ao);
            ldmA(al, uWl + ao);
            int brow = ks + (lane & 15), bcol = (lane >> 4)*8;
#pragma unroll
            for (int g = 0; g < 4; ++g){
                u32 bh[4], bl[4];
                u32 bo = (u32)(brow*72 + g*16 + bcol)*2;
                ldmBT(bh, uHh + bo);
                ldmBT(bl, uHl + bo);
#pragma unroll
                for (int h = 0; h < 2; ++h){
                    float* c = a2[g*2 + h];
                    mma16816(c, ah, bh[2*h], bh[2*h+1]);
                    mma16816(c, ah, bl[2*h], bl[2*h+1]);
                    mma16816(c, al, bh[2*h], bh[2*h+1]);
                }
            }
        }

        // epilogue for q_m
        int cp = wid*16 + rbase;
        u64 eoff0 = ((u64)(b*64 + cp)*512 + n)*64;
        u64 eoff1 = ((u64)(b*64 + cp + 8)*512 + n)*64;
        if (m == 4 || m == 9){
            __nv_bfloat16* wh = g_bf + (u64)(m == 4 ? 0 : 6)*BUFSZ;
            __nv_bfloat16* wl = wh + BUFSZ;
#pragma unroll
            for (int jj = 0; jj < 8; ++jj){
                int l = jj*8 + lbase;
                float* c = a2[jj];
                u32 h0, l0, h1, l1;
                split2(c[0], c[1], h0, l0);
                split2(c[2], c[3], h1, l1);
                *(u32*)(wh + eoff0 + l) = h0;
                *(u32*)(wl + eoff0 + l) = l0;
                *(u32*)(wh + eoff1 + l) = h1;
                *(u32*)(wl + eoff1 + l) = l1;
            }
        } else {
            float* dst = g_pool + (u64)m*BUFSZ;
#pragma unroll
            for (int jj = 0; jj < 8; ++jj){
                int l = jj*8 + lbase;
                float* c = a2[jj];
                *(float2*)(dst + eoff0 + l) = make_float2(c[0], c[1]);
                *(float2*)(dst + eoff1 + l) = make_float2(c[2], c[3]);
            }
        }
    }
}

// ---------------------------------------------------------------------------
// tensor-core (mma.sync) Horner node step: r' = q + (M - I) @ r
// M-I via split-bf16 (hi+lo), 3 MMA products (hh, hl, lh) into fp32 acc.
// blockIdx.z selects branch: asel+=z, qid+=5z, bslot+=6z, wslot+=6z.
// MODE 0: write r' as bf16 hi/lo (slots wslot, wslot+1)
// MODE 1: write r' as fp32 into ACC (buffer 12)
// MODE 2: out[..., l+6] = ACC + r' + bias  (l < 58)
// ---------------------------------------------------------------------------
template<int MODE>
__global__ __launch_bounds__(128)
void k_node_mma(int asel, int qid, int bslot, int wslot, float* __restrict__ outp){
    __shared__ __align__(16) __nv_bfloat16 sAh[128*40];
    __shared__ __align__(16) __nv_bfloat16 sAl[128*40];
    __shared__ __align__(16) __nv_bfloat16 sBh[32*72];
    __shared__ __align__(16) __nv_bfloat16 sBl[32*72];

    int z = blockIdx.z;
    asel += z; qid += 5*z; bslot += 6*z; wslot += 6*z;

    int tid = threadIdx.x, lane = tid & 31, wid = tid >> 5;
    int bc = blockIdx.x, v0c = blockIdx.y << 7;

    const __nv_bfloat16* Ah = g_Abf + (u64)(asel*2)*262144;
    const __nv_bfloat16* Al = Ah + 262144;
    const __nv_bfloat16* Bh = g_bf + (u64)bslot*BUFSZ + (u64)bc*32768;
    const __nv_bfloat16* Bl = Bh + BUFSZ;

    u32 uAh = smem_u32(sAh), uAl = smem_u32(sAl);
    u32 uBh = smem_u32(sBh), uBl = smem_u32(sBl);

    float acc[2][8][4];
#pragma unroll
    for (int m = 0; m < 2; ++m)
#pragma unroll
        for (int j = 0; j < 8; ++j)
#pragma unroll
            for (int e = 0; e < 4; ++e) acc[m][j][e] = 0.f;

    for (int kc = 0; kc < 16; ++kc){
        int w0 = kc*32;
#pragma unroll
        for (int i = 0; i < 4; ++i){
            int idx = i*128 + tid;
            int row = idx >> 2, seg = idx & 3;
            u64 goff = (u64)(v0c + row)*512 + w0 + seg*8;
            *(uint4*)(sAh + row*40 + seg*8) = *(const uint4*)(Ah + goff);
            *(uint4*)(sAl + row*40 + seg*8) = *(const uint4*)(Al + goff);
        }
#pragma unroll
        for (int i = 0; i < 2; ++i){
            int idx = i*128 + tid;
            int row = idx >> 3, seg = idx & 7;
            u64 goff = (u64)(w0 + row)*64 + seg*8;
            *(uint4*)(sBh + row*72 + seg*8) = *(const uint4*)(Bh + goff);
            *(uint4*)(sBl + row*72 + seg*8) = *(const uint4*)(Bl + goff);
        }
        __syncthreads();
#pragma unroll
        for (int ks = 0; ks < 32; ks += 16){
            u32 ah[2][4], al[2][4];
            int arow = lane & 15, acol = ks + (lane >> 4)*8;
#pragma unroll
            for (int m = 0; m < 2; ++m){
                u32 ao = (u32)((wid*32 + m*16 + arow)*40 + acol)*2;
                ldmA(ah[m], uAh + ao);
                ldmA(al[m], uAl + ao);
            }
            int brow = ks + (lane & 15), bcol = (lane >> 4)*8;
#pragma unroll
            for (int g = 0; g < 4; ++g){
                u32 bh[4], bl[4];
                u32 bo = (u32)(brow*72 + g*16 + bcol)*2;
                ldmBT(bh, uBh + bo);
                ldmBT(bl, uBl + bo);
#pragma unroll
                for (int m = 0; m < 2; ++m){
#pragma unroll
                    for (int h = 0; h < 2; ++h){
                        float* c = acc[m][g*2 + h];
                        mma16816(c, ah[m], bh[2*h], bh[2*h+1]);
                        mma16816(c, ah[m], bl[2*h], bl[2*h+1]);
                        mma16816(c, al[m], bh[2*h], bh[2*h+1]);
                    }
                }
            }
        }
        __syncthreads();
    }

    const float* qp = g_pool + (u64)qid*BUFSZ + (u64)bc*32768;
    int lbase = (lane & 3)*2, rbase = lane >> 2;
#pragma unroll
    for (int m = 0; m < 2; ++m){
        int v = v0c + wid*32 + m*16 + rbase;
#pragma unroll
        for (int jj = 0; jj < 8; ++jj){
            int l = jj*8 + lbase;
            float* c = acc[m][jj];
            float2 q0 = *(const float2*)(qp + (u64)v*64 + l);
            float2 q1 = *(const float2*)(qp + (u64)(v+8)*64 + l);
            float a0 = c[0] + q0.x, a1 = c[1] + q0.y;
            float a2 = c[2] + q1.x, a3 = c[3] + q1.y;
            if (MODE == 0){
                __nv_bfloat16* wh = g_bf + (u64)wslot*BUFSZ + (u64)bc*32768;
                __nv_bfloat16* wl = wh + BUFSZ;
                u32 h0, l0, h1, l1;
                split2(a0, a1, h0, l0);
                split2(a2, a3, h1, l1);
                *(u32*)(wh + (u64)v*64 + l) = h0;
                *(u32*)(wl + (u64)v*64 + l) = l0;
                *(u32*)(wh + (u64)(v+8)*64 + l) = h1;
                *(u32*)(wl + (u64)(v+8)*64 + l) = l1;
            } else if (MODE == 1){
                float* op = g_pool + 12ULL*BUFSZ + (u64)bc*32768;
                *(float2*)(op + (u64)v*64 + l) = make_float2(a0, a1);
                *(float2*)(op + (u64)(v+8)*64 + l) = make_float2(a2, a3);
            } else {
                const float* ap = g_pool + 12ULL*BUFSZ + (u64)bc*32768;
                float bia = g_bias[bc & 63];
                float* op = outp + (u64)bc*32768;
                a0 += ap[(u64)v*64 + l] + bia;
                a1 += ap[(u64)v*64 + l + 1] + bia;
                a2 += ap[(u64)(v+8)*64 + l] + bia;
                a3 += ap[(u64)(v+8)*64 + l + 1] + bia;
                if (l < 58)     op[(u64)v*64 + l + 6]       = a0;
                if (l + 1 < 58) op[(u64)v*64 + l + 7]       = a1;
                if (l < 58)     op[(u64)(v+8)*64 + l + 6]   = a2;
                if (l + 1 < 58) op[(u64)(v+8)*64 + l + 7]   = a3;
            }
        }
    }
}

__global__ void k_zeropad(float* __restrict__ outp){
    int i = blockIdx.x*256 + threadIdx.x;
    if (i < 8*64*512*6){
        int row = i / 6, t = i - row*6;
        outp[(u64)row*64 + t] = 0.f;
    }
}

// ---------------------------------------------------------------------------
extern "C" void kernel_launch(void* const* d_in, const int* in_sizes, int n_in,
                              void* d_out, int out_size){
    (void)in_sizes; (void)n_in; (void)out_size;
    const float* x   = (const float*)d_in[0];
    const float* adj = (const float*)d_in[1];
    float* out = (float*)d_out;

    k_deg  <<<512, 256>>>(adj);
    k_norm <<<512, 256>>>(adj);
    k_prepA<<<512, 256>>>();
    k_prep<<<64, 256>>>(
        (const float*)d_in[ 2], (const float*)d_in[ 3], (const float*)d_in[ 4], (const float*)d_in[ 5],
        (const float*)d_in[ 6], (const float*)d_in[ 7], (const float*)d_in[ 8], (const float*)d_in[ 9],
        (const float*)d_in[10], (const float*)d_in[11], (const float*)d_in[12], (const float*)d_in[13],
        (const float*)d_in[14], (const float*)d_in[15], (const float*)d_in[16], (const float*)d_in[17],
        (const float*)d_in[18], (const float*)d_in[19], (const float*)d_in[20], (const float*)d_in[21]);

    k_fused<<<4096, 128>>>(x);

    // Horner: branch0 seed slot 0 (q4), branch1 seed slot 6 (q9);
    // merged launches run both branches via gridDim.z = 2.
    dim3 ng3(512, 4, 2);
    k_node_mma<0><<<ng3, 128>>>(0, 3, 0, 2, nullptr);   // step 0 (both branches)
    k_node_mma<0><<<ng3, 128>>>(0, 2, 2, 4, nullptr);   // step 1
    k_node_mma<0><<<ng3, 128>>>(0, 1, 4, 2, nullptr);   // step 2
    dim3 ng(512, 4, 1);
    k_node_mma<1><<<ng, 128>>>(0, 0, 2, 0, nullptr);    // branch0 final -> ACC
    k_node_mma<2><<<ng, 128>>>(1, 5, 8, 0, out);        // branch1 final -> out

    k_zeropad<<<6144, 256>>>(out);
}

// round 9
// speedup vs baseline: 2.4840x; 1.1565x over previous
#include <cuda_runtime.h>
#include <cuda_bf16.h>

typedef unsigned long long u64;
typedef unsigned int u32;

// ---------------------------------------------------------------------------
// Shapes: B=8, C=64, N=512, T=64, valid L=58 (stored padded to 64).
// fp32 pool: q0..q9 (ids 0-9; 4 and 9 unused as fp32), ACC=12.
// bf16 pool slots (BUFSZ each):
//   0/1 seed1(q4) hi/lo, 2/3 & 4/5 branch0 ping-pong,
//   6/7 seed2(q9) hi/lo, 8/9 & 10/11 branch1 ping-pong.
// ---------------------------------------------------------------------------
#define BUFSZ (8ULL*64ULL*512ULL*64ULL)

__device__ float g_pool[13ULL*BUFSZ];
__device__ __nv_bfloat16 g_bf[12ULL*BUFSZ];
__device__ __nv_bfloat16 g_Abf[4ULL*512*512];  // [asel*2+hi/lo][v][w] of (M - I)

__device__ float g_An [512*512];   // [w][v] = M1[v][w]
__device__ float g_AnT[512*512];   // [w][v] = M2[v][w]
__device__ float g_rd1[512], g_rd2[512];
__device__ __nv_bfloat16 g_W7h[128*448];   // [o][kd] hi
__device__ __nv_bfloat16 g_W7l[128*448];   // [o][kd] lo
__device__ float g_b7[128];
__device__ __nv_bfloat16 g_Wqh[10*64*64];  // [m][out][in] hi  (MMA A-row = out)
__device__ __nv_bfloat16 g_Wql[10*64*64];  // [m][out][in] lo
__device__ float g_bias[64];

// ---------------------------------------------------------------------------
// helpers
// ---------------------------------------------------------------------------
__device__ __forceinline__ u32 smem_u32(const void* p){
    u32 a;
    asm("{ .reg .u64 t; cvta.to.shared.u64 t, %1; cvt.u32.u64 %0, t; }" : "=r"(a) : "l"(p));
    return a;
}
// split a pair of fp32 into packed bf16 hi / bf16 lo
__device__ __forceinline__ void split2(float a0, float a1, u32& hi, u32& lo){
    __nv_bfloat16 h0 = __float2bfloat16(a0);
    __nv_bfloat16 h1 = __float2bfloat16(a1);
    float r0 = a0 - __bfloat162float(h0);
    float r1 = a1 - __bfloat162float(h1);
    union { __nv_bfloat162 v; u32 u; } ch, cl;
    ch.v = __halves2bfloat162(h0, h1);
    cl.v = __halves2bfloat162(__float2bfloat16(r0), __float2bfloat16(r1));
    hi = ch.u; lo = cl.u;
}

// ---------------------------------------------------------------------------
// mma.sync / ldmatrix / cp.async wrappers (baseline PTX, legal on compute_103)
// ---------------------------------------------------------------------------
__device__ __forceinline__ void mma16816(float* c, const u32* a, u32 b0, u32 b1){
    asm volatile(
        "mma.sync.aligned.m16n8k16.row.col.f32.bf16.bf16.f32 "
        "{%0,%1,%2,%3}, {%4,%5,%6,%7}, {%8,%9}, {%0,%1,%2,%3};"
        : "+f"(c[0]), "+f"(c[1]), "+f"(c[2]), "+f"(c[3])
        : "r"(a[0]), "r"(a[1]), "r"(a[2]), "r"(a[3]), "r"(b0), "r"(b1));
}
__device__ __forceinline__ void ldmA(u32* r, u32 addr){
    asm volatile("ldmatrix.sync.aligned.m8n8.x4.shared.b16 {%0,%1,%2,%3}, [%4];"
        : "=r"(r[0]), "=r"(r[1]), "=r"(r[2]), "=r"(r[3]) : "r"(addr));
}
__device__ __forceinline__ void ldmBT(u32* r, u32 addr){
    asm volatile("ldmatrix.sync.aligned.m8n8.x4.trans.shared.b16 {%0,%1,%2,%3}, [%4];"
        : "=r"(r[0]), "=r"(r[1]), "=r"(r[2]), "=r"(r[3]) : "r"(addr));
}
__device__ __forceinline__ void cpa16(u32 dst, const void* src){
    asm volatile("cp.async.cg.shared.global [%0], [%1], 16;" :: "r"(dst), "l"(src));
}
__device__ __forceinline__ void cpa_commit(){
    asm volatile("cp.async.commit_group;" ::: "memory");
}
template<int N>
__device__ __forceinline__ void cpa_wait(){
    asm volatile("cp.async.wait_group %0;" :: "n"(N) : "memory");
}

// ---------------------------------------------------------------------------
// degrees + normalized adjacencies
// ---------------------------------------------------------------------------
__global__ void k_deg(const float* __restrict__ adj){
    int v = blockIdx.x, tid = threadIdx.x;
    float s1 = 0.f, s2 = 0.f;
    for (int w = tid; w < 512; w += 256){
        s1 += adj[v*512 + w];
        s2 += adj[w*512 + v];
    }
    __shared__ float r1[256], r2[256];
    r1[tid] = s1; r2[tid] = s2;
    __syncthreads();
    for (int s = 128; s > 0; s >>= 1){
        if (tid < s){ r1[tid] += r1[tid+s]; r2[tid] += r2[tid+s]; }
        __syncthreads();
    }
    if (tid == 0){
        g_rd1[v] = rsqrtf(r1[0] + 1.f);
        g_rd2[v] = rsqrtf(r2[0] + 1.f);
    }
}

__global__ void k_norm(const float* __restrict__ adj){
    int w = blockIdx.x;
    float dw1 = g_rd1[w], dw2 = g_rd2[w];
    for (int v = threadIdx.x; v < 512; v += 256){
        float e = (v == w) ? 1.f : 0.f;
        g_An [w*512 + v] = g_rd1[v] * (adj[v*512 + w] + e) * dw1;
        g_AnT[w*512 + v] = g_rd2[v] * (adj[w*512 + v] + e) * dw2;
    }
}

// split (An - I)/(AnT - I) into bf16 hi/lo in [v][w] (K-major) layout
__global__ void k_prepA(){
    int v = blockIdx.x;
    for (int w = threadIdx.x; w < 512; w += 256){
        float e = (v == w) ? 1.f : 0.f;
        float a1 = g_An [w*512 + v] - e;
        float a2 = g_AnT[w*512 + v] - e;
        __nv_bfloat16 h1 = __float2bfloat16(a1);
        __nv_bfloat16 l1 = __float2bfloat16(a1 - __bfloat162float(h1));
        __nv_bfloat16 h2 = __float2bfloat16(a2);
        __nv_bfloat16 l2 = __float2bfloat16(a2 - __bfloat162float(h2));
        g_Abf[0ULL*262144 + v*512 + w] = h1;
        g_Abf[1ULL*262144 + v*512 + w] = l1;
        g_Abf[2ULL*262144 + v*512 + w] = h2;
        g_Abf[3ULL*262144 + v*512 + w] = l2;
    }
}

// ---------------------------------------------------------------------------
// prep: pad inception weights to k=7 (windows end at l+6), build Horner W'_j,
// split everything to bf16 hi/lo in MMA-friendly layouts.
// ---------------------------------------------------------------------------
__global__ void k_prep(const float* i1w0,const float* i1b0,const float* i1w1,const float* i1b1,
                       const float* i1w2,const float* i1b2,const float* i1w3,const float* i1b3,
                       const float* i2w0,const float* i2b0,const float* i2w1,const float* i2b1,
                       const float* i2w2,const float* i2b2,const float* i2w3,const float* i2b3,
                       const float* m1w,const float* m1b,const float* m2w,const float* m2b){
    int g0 = blockIdx.x*256 + threadIdx.x, gstr = gridDim.x*256;
    const float* WS[8] = {i1w0,i1w1,i1w2,i1w3,i2w0,i2w1,i2w2,i2w3};
    const float* BS[8] = {i1b0,i1b1,i1b2,i1b3,i2b0,i2b1,i2b2,i2b3};
    const int KERN[4] = {2,3,6,7};

    // W7: [o][kd], kd = c*7 + tau
    for (int idx = g0; idx < 128*448; idx += gstr){
        int o = idx / 448, kd = idx - o*448;
        int c = kd / 7, tau = kd - c*7;
        int br = o >> 6, j = (o >> 4) & 3, oc = o & 15;
        int k = KERN[j];
        int t = tau - (7 - k);
        float v = (t >= 0) ? WS[br*4 + j][(oc*64 + c)*k + t] : 0.f;
        __nv_bfloat16 h = __float2bfloat16(v);
        g_W7h[idx] = h;
        g_W7l[idx] = __float2bfloat16(v - __bfloat162float(h));
    }
    for (int idx = g0; idx < 128; idx += gstr){
        int br = idx >> 6, j = (idx >> 4) & 3, oc = idx & 15;
        g_b7[idx] = BS[br*4 + j][oc];
    }
    for (int idx = g0; idx < 64; idx += gstr)
        g_bias[idx] = m1b[idx] + m2b[idx];

    const float COEF[5][5] = {
        {1.f, 1.f,      1.f,      1.f,      1.f     },
        {0.f, 1.f/3.f,  2.f/3.f,  1.f,      1.f     },
        {0.f, 0.f,      1.f/3.f,  1.f/3.f,  0.5f    },
        {0.f, 0.f,      0.f,      1.f/3.f,  1.f/6.f },
        {0.f, 0.f,      0.f,      0.f,      1.f/24.f}};
    // Wq bf16 stored [m][out=c][in=cp] so MMA A-fragment rows are outputs.
    for (int idx = g0; idx < 10*4096; idx += gstr){
        int m = idx >> 12, cp = (idx >> 6) & 63, c = idx & 63;
        int j = m % 5;
        const float* mw = (m < 5) ? m1w : m2w;
        float s = 0.f;
#pragma unroll
        for (int g = 0; g < 5; ++g)
            s += COEF[j][g] * mw[c*320 + g*64 + cp];
        __nv_bfloat16 h = __float2bfloat16(s);
        int widx = (m << 12) + (c << 6) + cp;   // [m][out][in]
        g_Wqh[widx] = h;
        g_Wql[widx] = __float2bfloat16(s - __bfloat162float(h));
    }
}

// ---------------------------------------------------------------------------
// FUSED inception + gate + qgen, all tensor-core (mma.sync split-bf16).
// ---------------------------------------------------------------------------
__global__ __launch_bounds__(128) void k_fused(const float* __restrict__ x){
    __shared__ __align__(16) char sm[38912];
    // stage-1 overlays
    __nv_bfloat16* sAh = (__nv_bfloat16*)(sm);            // [128][40]
    __nv_bfloat16* sAl = (__nv_bfloat16*)(sm + 10240);    // [128][40]
    __nv_bfloat16* sBh = (__nv_bfloat16*)(sm + 20480);    // [32][72]
    __nv_bfloat16* sBl = (__nv_bfloat16*)(sm + 25088);    // [32][72]
    // gate / stage-2 overlays
    float*         sG  = (float*)(sm);                    // [64][72] fp32
    __nv_bfloat16* sWh = (__nv_bfloat16*)(sm);            // [64][72]
    __nv_bfloat16* sWl = (__nv_bfloat16*)(sm + 9216);     // [64][72]
    __nv_bfloat16* sHh = (__nv_bfloat16*)(sm + 20480);    // [64][72]
    __nv_bfloat16* sHl = (__nv_bfloat16*)(sm + 29696);    // [64][72]

    int bn = blockIdx.x;
    int b = bn >> 9, n = bn & 511;
    int tid = threadIdx.x, lane = tid & 31, wid = tid >> 5;
    const float* xb = x + (u64)b*64*32768 + (u64)n*64;   // channel stride 512*64

    u32 uAh = smem_u32(sAh), uAl = smem_u32(sAl);
    u32 uBh = smem_u32(sBh), uBl = smem_u32(sBl);
    u32 uWh = smem_u32(sWh), uWl = smem_u32(sWl);
    u32 uHh = smem_u32(sHh), uHl = smem_u32(sHl);

    float acc[2][8][4];
#pragma unroll
    for (int m = 0; m < 2; ++m)
#pragma unroll
        for (int j = 0; j < 8; ++j)
#pragma unroll
            for (int e = 0; e < 4; ++e) acc[m][j][e] = 0.f;

    // ---------------- stage 1: inception GEMM (K = 448, 14 chunks of 32) ----
    for (int kc = 0; kc < 14; ++kc){
        int w0 = kc*32;
#pragma unroll
        for (int i = 0; i < 4; ++i){
            int idx = i*128 + tid;
            int row = idx >> 2, seg = idx & 3;
            *(uint4*)(sAh + row*40 + seg*8) = *(const uint4*)(g_W7h + row*448 + w0 + seg*8);
            *(uint4*)(sAl + row*40 + seg*8) = *(const uint4*)(g_W7l + row*448 + w0 + seg*8);
        }
        // B: im2col rows kd = w0+row, split fp32 -> bf16 hi/lo
#pragma unroll
        for (int i = 0; i < 8; ++i){
            int idx = i*128 + tid;          // (row, lpair): 32 x 32
            int row = idx >> 5, lp = idx & 31, l = lp*2;
            int kd = w0 + row;
            int c = kd / 7, tau = kd - c*7;
            int t = l + tau;
            float v0 = (t < 64) ? xb[(u64)c*32768 + t] : 0.f;
            float v1 = (t + 1 < 64) ? xb[(u64)c*32768 + t + 1] : 0.f;
            u32 h, lo; split2(v0, v1, h, lo);
            *(u32*)(sBh + row*72 + l) = h;
            *(u32*)(sBl + row*72 + l) = lo;
        }
        __syncthreads();
#pragma unroll
        for (int ks = 0; ks < 32; ks += 16){
            u32 ah[2][4], al[2][4];
            int arow = lane & 15, acol = ks + (lane >> 4)*8;
#pragma unroll
            for (int m = 0; m < 2; ++m){
                u32 ao = (u32)((wid*32 + m*16 + arow)*40 + acol)*2;
                ldmA(ah[m], uAh + ao);
                ldmA(al[m], uAl + ao);
            }
            int brow = ks + (lane & 15), bcol = (lane >> 4)*8;
#pragma unroll
            for (int g = 0; g < 4; ++g){
                u32 bh[4], bl[4];
                u32 bo = (u32)(brow*72 + g*16 + bcol)*2;
                ldmBT(bh, uBh + bo);
                ldmBT(bl, uBl + bo);
#pragma unroll
                for (int m = 0; m < 2; ++m){
#pragma unroll
                    for (int h = 0; h < 2; ++h){
                        float* c = acc[m][g*2 + h];
                        mma16816(c, ah[m], bh[2*h], bh[2*h+1]);
                        mma16816(c, ah[m], bl[2*h], bl[2*h+1]);
                        mma16816(c, al[m], bh[2*h], bh[2*h+1]);
                    }
                }
            }
        }
        __syncthreads();
    }

    // ---------------- gate: h = tanh(filt) * sigmoid(gate) ------------------
    int lbase = (lane & 3)*2, rbase = lane >> 2;
    if (wid >= 2){   // gate rows: o = 64..127 -> write sigmoid to sG
#pragma unroll
        for (int m = 0; m < 2; ++m){
            int o = wid*32 + m*16 + rbase;
#pragma unroll
            for (int jj = 0; jj < 8; ++jj){
                int l = jj*8 + lbase;
                float* c = acc[m][jj];
                float b0 = g_b7[o], b1 = g_b7[o + 8];
                float2 g0, g1;
                g0.x = 1.f/(1.f + expf(-(c[0] + b0)));
                g0.y = 1.f/(1.f + expf(-(c[1] + b0)));
                g1.x = 1.f/(1.f + expf(-(c[2] + b1)));
                g1.y = 1.f/(1.f + expf(-(c[3] + b1)));
                *(float2*)(sG + (o - 64)*72 + l) = g0;
                *(float2*)(sG + (o - 64 + 8)*72 + l) = g1;
            }
        }
    }
    __syncthreads();
    if (wid < 2){    // filt rows: o = c = 0..63 -> h split to sHh/sHl
#pragma unroll
        for (int m = 0; m < 2; ++m){
            int c0 = wid*32 + m*16 + rbase;
#pragma unroll
            for (int jj = 0; jj < 8; ++jj){
                int l = jj*8 + lbase;
                float* c = acc[m][jj];
                float b0 = g_b7[c0], b1 = g_b7[c0 + 8];
                float2 ga = *(const float2*)(sG + c0*72 + l);
                float2 gb = *(const float2*)(sG + (c0 + 8)*72 + l);
                float h0 = tanhf(c[0] + b0) * ga.x;
                float h1 = tanhf(c[1] + b0) * ga.y;
                float h2 = tanhf(c[2] + b1) * gb.x;
                float h3 = tanhf(c[3] + b1) * gb.y;
                u32 ph0, pl0, ph1, pl1;
                split2(h0, h1, ph0, pl0);
                split2(h2, h3, ph1, pl1);
                *(u32*)(sHh + c0*72 + l) = ph0;
                *(u32*)(sHl + c0*72 + l) = pl0;
                *(u32*)(sHh + (c0 + 8)*72 + l) = ph1;
                *(u32*)(sHl + (c0 + 8)*72 + l) = pl1;
            }
        }
    }

    // ---------------- stage 2: q_m = W'_m @ h, m = 0..9 ---------------------
    for (int m = 0; m < 10; ++m){
        __syncthreads();   // sH visible (first iter); sW safe to overwrite
#pragma unroll
        for (int i = 0; i < 4; ++i){
            int idx = i*128 + tid;
            int row = idx >> 3, seg = idx & 7;
            *(uint4*)(sWh + row*72 + seg*8) = *(const uint4*)(g_Wqh + m*4096 + row*64 + seg*8);
            *(uint4*)(sWl + row*72 + seg*8) = *(const uint4*)(g_Wql + m*4096 + row*64 + seg*8);
        }
        __syncthreads();

        float a2[8][4];
#pragma unroll
        for (int j = 0; j < 8; ++j)
#pragma unroll
            for (int e = 0; e < 4; ++e) a2[j][e] = 0.f;

#pragma unroll
        for (int ks = 0; ks < 64; ks += 16){
            u32 ah[4], al[4];
            u32 ao = (u32)((wid*16 + (lane & 15))*72 + ks + (lane >> 4)*8)*2;
            ldmA(ah, uWh + ao);
            ldmA(al, uWl + ao);
            int brow = ks + (lane & 15), bcol = (lane >> 4)*8;
#pragma unroll
            for (int g = 0; g < 4; ++g){
                u32 bh[4], bl[4];
                u32 bo = (u32)(brow*72 + g*16 + bcol)*2;
                ldmBT(bh, uHh + bo);
                ldmBT(bl, uHl + bo);
#pragma unroll
                for (int h = 0; h < 2; ++h){
                    float* c = a2[g*2 + h];
                    mma16816(c, ah, bh[2*h], bh[2*h+1]);
                    mma16816(c, ah, bl[2*h], bl[2*h+1]);
                    mma16816(c, al, bh[2*h], bh[2*h+1]);
                }
            }
        }

        // epilogue for q_m
        int cp = wid*16 + rbase;
        u64 eoff0 = ((u64)(b*64 + cp)*512 + n)*64;
        u64 eoff1 = ((u64)(b*64 + cp + 8)*512 + n)*64;
        if (m == 4 || m == 9){
            __nv_bfloat16* wh = g_bf + (u64)(m == 4 ? 0 : 6)*BUFSZ;
            __nv_bfloat16* wl = wh + BUFSZ;
#pragma unroll
            for (int jj = 0; jj < 8; ++jj){
                int l = jj*8 + lbase;
                float* c = a2[jj];
                u32 h0, l0, h1, l1;
                split2(c[0], c[1], h0, l0);
                split2(c[2], c[3], h1, l1);
                *(u32*)(wh + eoff0 + l) = h0;
                *(u32*)(wl + eoff0 + l) = l0;
                *(u32*)(wh + eoff1 + l) = h1;
                *(u32*)(wl + eoff1 + l) = l1;
            }
        } else {
            float* dst = g_pool + (u64)m*BUFSZ;
#pragma unroll
            for (int jj = 0; jj < 8; ++jj){
                int l = jj*8 + lbase;
                float* c = a2[jj];
                *(float2*)(dst + eoff0 + l) = make_float2(c[0], c[1]);
                *(float2*)(dst + eoff1 + l) = make_float2(c[2], c[3]);
            }
        }
    }
}

// ---------------------------------------------------------------------------
// tensor-core (mma.sync) Horner node step: r' = q + (M - I) @ r
// 2-stage cp.async pipeline over 16 K-chunks of 32.
// Dynamic smem: 2 stages x 29696B: [Ah 10240][Al 10240][Bh 4608][Bl 4608]
// blockIdx.z selects branch: asel+=z, qid+=5z, bslot+=6z, wslot+=6z.
// MODE 0: write r' as bf16 hi/lo; MODE 1: fp32 -> ACC; MODE 2: final output.
// ---------------------------------------------------------------------------
#define NODE_SST 29696
#define NODE_SMEM (2*NODE_SST)

__device__ __forceinline__ void node_prefetch(
    u32 sb, const __nv_bfloat16* Ah, const __nv_bfloat16* Al,
    const __nv_bfloat16* Bh, const __nv_bfloat16* Bl,
    int w0, int v0c, int tid){
#pragma unroll
    for (int i = 0; i < 4; ++i){
        int idx = i*128 + tid;
        int row = idx >> 2, seg = idx & 3;
        u64 goff = (u64)(v0c + row)*512 + w0 + seg*8;
        cpa16(sb + row*80 + seg*16, Ah + goff);
        cpa16(sb + 10240 + row*80 + seg*16, Al + goff);
    }
#pragma unroll
    for (int i = 0; i < 2; ++i){
        int idx = i*128 + tid;
        int row = idx >> 3, seg = idx & 7;
        u64 goff = (u64)(w0 + row)*64 + seg*8;
        cpa16(sb + 20480 + row*144 + seg*16, Bh + goff);
        cpa16(sb + 25088 + row*144 + seg*16, Bl + goff);
    }
}

template<int MODE>
__global__ __launch_bounds__(128)
void k_node_mma(int asel, int qid, int bslot, int wslot, float* __restrict__ outp){
    extern __shared__ __align__(16) char smn[];
    u32 base = smem_u32(smn);

    int z = blockIdx.z;
    asel += z; qid += 5*z; bslot += 6*z; wslot += 6*z;

    int tid = threadIdx.x, lane = tid & 31, wid = tid >> 5;
    int bc = blockIdx.x, v0c = blockIdx.y << 7;

    const __nv_bfloat16* Ah = g_Abf + (u64)(asel*2)*262144;
    const __nv_bfloat16* Al = Ah + 262144;
    const __nv_bfloat16* Bh = g_bf + (u64)bslot*BUFSZ + (u64)bc*32768;
    const __nv_bfloat16* Bl = Bh + BUFSZ;

    float acc[2][8][4];
#pragma unroll
    for (int m = 0; m < 2; ++m)
#pragma unroll
        for (int j = 0; j < 8; ++j)
#pragma unroll
            for (int e = 0; e < 4; ++e) acc[m][j][e] = 0.f;

    // prologue: prefetch chunk 0
    node_prefetch(base, Ah, Al, Bh, Bl, 0, v0c, tid);
    cpa_commit();

    for (int kc = 0; kc < 16; ++kc){
        if (kc < 15){
            node_prefetch(base + ((kc+1)&1)*NODE_SST, Ah, Al, Bh, Bl,
                          (kc+1)*32, v0c, tid);
            cpa_commit();
            cpa_wait<1>();
        } else {
            cpa_wait<0>();
        }
        __syncthreads();

        u32 sb = base + (kc&1)*NODE_SST;
        u32 uAh = sb, uAl = sb + 10240, uBh = sb + 20480, uBl = sb + 25088;
#pragma unroll
        for (int ks = 0; ks < 32; ks += 16){
            u32 ah[2][4], al[2][4];
            int arow = lane & 15, acol = ks + (lane >> 4)*8;
#pragma unroll
            for (int m = 0; m < 2; ++m){
                u32 ao = (u32)((wid*32 + m*16 + arow)*40 + acol)*2;
                ldmA(ah[m], uAh + ao);
                ldmA(al[m], uAl + ao);
            }
            int brow = ks + (lane & 15), bcol = (lane >> 4)*8;
#pragma unroll
            for (int g = 0; g < 4; ++g){
                u32 bh[4], bl[4];
                u32 bo = (u32)(brow*72 + g*16 + bcol)*2;
                ldmBT(bh, uBh + bo);
                ldmBT(bl, uBl + bo);
#pragma unroll
                for (int m = 0; m < 2; ++m){
#pragma unroll
                    for (int h = 0; h < 2; ++h){
                        float* c = acc[m][g*2 + h];
                        mma16816(c, ah[m], bh[2*h], bh[2*h+1]);
                        mma16816(c, ah[m], bl[2*h], bl[2*h+1]);
                        mma16816(c, al[m], bh[2*h], bh[2*h+1]);
                    }
                }
            }
        }
        __syncthreads();   // all reads of stage kc done before it is overwritten
    }

    const float* qp = g_pool + (u64)qid*BUFSZ + (u64)bc*32768;
    int lbase = (lane & 3)*2, rbase = lane >> 2;
#pragma unroll
    for (int m = 0; m < 2; ++m){
        int v = v0c + wid*32 + m*16 + rbase;
#pragma unroll
        for (int jj = 0; jj < 8; ++jj){
            int l = jj*8 + lbase;
            float* c = acc[m][jj];
            float2 q0 = *(const float2*)(qp + (u64)v*64 + l);
            float2 q1 = *(const float2*)(qp + (u64)(v+8)*64 + l);
            float a0 = c[0] + q0.x, a1 = c[1] + q0.y;
            float a2 = c[2] + q1.x, a3 = c[3] + q1.y;
            if (MODE == 0){
                __nv_bfloat16* wh = g_bf + (u64)wslot*BUFSZ + (u64)bc*32768;
                __nv_bfloat16* wl = wh + BUFSZ;
                u32 h0, l0, h1, l1;
                split2(a0, a1, h0, l0);
                split2(a2, a3, h1, l1);
                *(u32*)(wh + (u64)v*64 + l) = h0;
                *(u32*)(wl + (u64)v*64 + l) = l0;
                *(u32*)(wh + (u64)(v+8)*64 + l) = h1;
                *(u32*)(wl + (u64)(v+8)*64 + l) = l1;
            } else if (MODE == 1){
                float* op = g_pool + 12ULL*BUFSZ + (u64)bc*32768;
                *(float2*)(op + (u64)v*64 + l) = make_float2(a0, a1);
                *(float2*)(op + (u64)(v+8)*64 + l) = make_float2(a2, a3);
            } else {
                const float* ap = g_pool + 12ULL*BUFSZ + (u64)bc*32768;
                float bia = g_bias[bc & 63];
                float* op = outp + (u64)bc*32768;
                a0 += ap[(u64)v*64 + l] + bia;
                a1 += ap[(u64)v*64 + l + 1] + bia;
                a2 += ap[(u64)(v+8)*64 + l] + bia;
                a3 += ap[(u64)(v+8)*64 + l + 1] + bia;
                if (l < 58)     op[(u64)v*64 + l + 6]       = a0;
                if (l + 1 < 58) op[(u64)v*64 + l + 7]       = a1;
                if (l < 58)     op[(u64)(v+8)*64 + l + 6]   = a2;
                if (l + 1 < 58) op[(u64)(v+8)*64 + l + 7]   = a3;
            }
        }
    }
}

__global__ void k_zeropad(float* __restrict__ outp){
    int i = blockIdx.x*256 + threadIdx.x;
    if (i < 8*64*512*6){
        int row = i / 6, t = i - row*6;
        outp[(u64)row*64 + t] = 0.f;
    }
}

// ---------------------------------------------------------------------------
extern "C" void kernel_launch(void* const* d_in, const int* in_sizes, int n_in,
                              void* d_out, int out_size){
    (void)in_sizes; (void)n_in; (void)out_size;
    const float* x   = (const float*)d_in[0];
    const float* adj = (const float*)d_in[1];
    float* out = (float*)d_out;

    // allow >48KB dynamic smem for the node kernels (idempotent)
    cudaFuncSetAttribute(k_node_mma<0>, cudaFuncAttributeMaxDynamicSharedMemorySize, NODE_SMEM);
    cudaFuncSetAttribute(k_node_mma<1>, cudaFuncAttributeMaxDynamicSharedMemorySize, NODE_SMEM);
    cudaFuncSetAttribute(k_node_mma<2>, cudaFuncAttributeMaxDynamicSharedMemorySize, NODE_SMEM);

    k_deg  <<<512, 256>>>(adj);
    k_norm <<<512, 256>>>(adj);
    k_prepA<<<512, 256>>>();
    k_prep<<<64, 256>>>(
        (const float*)d_in[ 2], (const float*)d_in[ 3], (const float*)d_in[ 4], (const float*)d_in[ 5],
        (const float*)d_in[ 6], (const float*)d_in[ 7], (const float*)d_in[ 8], (const float*)d_in[ 9],
        (const float*)d_in[10], (const float*)d_in[11], (const float*)d_in[12], (const float*)d_in[13],
        (const float*)d_in[14], (const float*)d_in[15], (const float*)d_in[16], (const float*)d_in[17],
        (const float*)d_in[18], (const float*)d_in[19], (const float*)d_in[20], (const float*)d_in[21]);

    k_fused<<<4096, 128>>>(x);

    // Horner: branch0 seed slot 0 (q4), branch1 seed slot 6 (q9);
    // merged launches run both branches via gridDim.z = 2.
    dim3 ng3(512, 4, 2);
    k_node_mma<0><<<ng3, 128, NODE_SMEM>>>(0, 3, 0, 2, nullptr);   // step 0
    k_node_mma<0><<<ng3, 128, NODE_SMEM>>>(0, 2, 2, 4, nullptr);   // step 1
    k_node_mma<0><<<ng3, 128, NODE_SMEM>>>(0, 1, 4, 2, nullptr);   // step 2
    dim3 ng(512, 4, 1);
    k_node_mma<1><<<ng, 128, NODE_SMEM>>>(0, 0, 2, 0, nullptr);    // b0 final -> ACC
    k_node_mma<2><<<ng, 128, NODE_SMEM>>>(1, 5, 8, 0, out);        // b1 final -> out

    k_zeropad<<<6144, 256>>>(out);
}

// round 10
// speedup vs baseline: 2.5159x; 1.0128x over previous
#include <cuda_runtime.h>
#include <cuda_bf16.h>

typedef unsigned long long u64;
typedef unsigned int u32;

// ---------------------------------------------------------------------------
// Shapes: B=8, C=64, N=512, T=64, valid L=58 (stored padded to 64).
// fp32 pool: q0..q9 (ids 0-9; 4 and 9 unused as fp32), ACC=12.
// bf16 pool slots (BUFSZ each):
//   0/1 seed1(q4) hi/lo, 2/3 & 4/5 branch0 ping-pong,
//   6/7 seed2(q9) hi/lo, 8/9 & 10/11 branch1 ping-pong.
// ---------------------------------------------------------------------------
#define BUFSZ (8ULL*64ULL*512ULL*64ULL)

__device__ float g_pool[13ULL*BUFSZ];
__device__ __nv_bfloat16 g_bf[12ULL*BUFSZ];
__device__ __nv_bfloat16 g_Abf[4ULL*512*512];  // [asel*2+hi/lo][v][w] of (M - I)

__device__ float g_An [512*512];   // [w][v] = M1[v][w]
__device__ float g_AnT[512*512];   // [w][v] = M2[v][w]
__device__ float g_rd1[512], g_rd2[512];
__device__ __nv_bfloat16 g_W7h[128*448];   // [o][kd] hi
__device__ __nv_bfloat16 g_W7l[128*448];   // [o][kd] lo
__device__ float g_b7[128];
__device__ __nv_bfloat16 g_Wqh[10*64*64];  // [m][out][in] hi  (MMA A-row = out)
__device__ __nv_bfloat16 g_Wql[10*64*64];  // [m][out][in] lo
__device__ float g_bias[64];

// ---------------------------------------------------------------------------
// helpers
// ---------------------------------------------------------------------------
__device__ __forceinline__ u32 smem_u32(const void* p){
    u32 a;
    asm("{ .reg .u64 t; cvta.to.shared.u64 t, %1; cvt.u32.u64 %0, t; }" : "=r"(a) : "l"(p));
    return a;
}
// split a pair of fp32 into packed bf16 hi / bf16 lo
__device__ __forceinline__ void split2(float a0, float a1, u32& hi, u32& lo){
    __nv_bfloat16 h0 = __float2bfloat16(a0);
    __nv_bfloat16 h1 = __float2bfloat16(a1);
    float r0 = a0 - __bfloat162float(h0);
    float r1 = a1 - __bfloat162float(h1);
    union { __nv_bfloat162 v; u32 u; } ch, cl;
    ch.v = __halves2bfloat162(h0, h1);
    cl.v = __halves2bfloat162(__float2bfloat16(r0), __float2bfloat16(r1));
    hi = ch.u; lo = cl.u;
}

// ---------------------------------------------------------------------------
// mma.sync / ldmatrix / cp.async wrappers (baseline PTX, legal on compute_103)
// ---------------------------------------------------------------------------
__device__ __forceinline__ void mma16816(float* c, const u32* a, u32 b0, u32 b1){
    asm volatile(
        "mma.sync.aligned.m16n8k16.row.col.f32.bf16.bf16.f32 "
        "{%0,%1,%2,%3}, {%4,%5,%6,%7}, {%8,%9}, {%0,%1,%2,%3};"
        : "+f"(c[0]), "+f"(c[1]), "+f"(c[2]), "+f"(c[3])
        : "r"(a[0]), "r"(a[1]), "r"(a[2]), "r"(a[3]), "r"(b0), "r"(b1));
}
__device__ __forceinline__ void ldmA(u32* r, u32 addr){
    asm volatile("ldmatrix.sync.aligned.m8n8.x4.shared.b16 {%0,%1,%2,%3}, [%4];"
        : "=r"(r[0]), "=r"(r[1]), "=r"(r[2]), "=r"(r[3]) : "r"(addr));
}
__device__ __forceinline__ void ldmBT(u32* r, u32 addr){
    asm volatile("ldmatrix.sync.aligned.m8n8.x4.trans.shared.b16 {%0,%1,%2,%3}, [%4];"
        : "=r"(r[0]), "=r"(r[1]), "=r"(r[2]), "=r"(r[3]) : "r"(addr));
}
__device__ __forceinline__ void cpa16(u32 dst, const void* src){
    asm volatile("cp.async.cg.shared.global [%0], [%1], 16;" :: "r"(dst), "l"(src));
}
__device__ __forceinline__ void cpa_commit(){
    asm volatile("cp.async.commit_group;" ::: "memory");
}
template<int N>
__device__ __forceinline__ void cpa_wait(){
    asm volatile("cp.async.wait_group %0;" :: "n"(N) : "memory");
}

// ---------------------------------------------------------------------------
// degrees + normalized adjacencies
// ---------------------------------------------------------------------------
__global__ void k_deg(const float* __restrict__ adj){
    int v = blockIdx.x, tid = threadIdx.x;
    float s1 = 0.f, s2 = 0.f;
    for (int w = tid; w < 512; w += 256){
        s1 += adj[v*512 + w];
        s2 += adj[w*512 + v];
    }
    __shared__ float r1[256], r2[256];
    r1[tid] = s1; r2[tid] = s2;
    __syncthreads();
    for (int s = 128; s > 0; s >>= 1){
        if (tid < s){ r1[tid] += r1[tid+s]; r2[tid] += r2[tid+s]; }
        __syncthreads();
    }
    if (tid == 0){
        g_rd1[v] = rsqrtf(r1[0] + 1.f);
        g_rd2[v] = rsqrtf(r2[0] + 1.f);
    }
}

__global__ void k_norm(const float* __restrict__ adj){
    int w = blockIdx.x;
    float dw1 = g_rd1[w], dw2 = g_rd2[w];
    for (int v = threadIdx.x; v < 512; v += 256){
        float e = (v == w) ? 1.f : 0.f;
        g_An [w*512 + v] = g_rd1[v] * (adj[v*512 + w] + e) * dw1;
        g_AnT[w*512 + v] = g_rd2[v] * (adj[w*512 + v] + e) * dw2;
    }
}

// split (An - I)/(AnT - I) into bf16 hi/lo in [v][w] (K-major) layout
__global__ void k_prepA(){
    int v = blockIdx.x;
    for (int w = threadIdx.x; w < 512; w += 256){
        float e = (v == w) ? 1.f : 0.f;
        float a1 = g_An [w*512 + v] - e;
        float a2 = g_AnT[w*512 + v] - e;
        __nv_bfloat16 h1 = __float2bfloat16(a1);
        __nv_bfloat16 l1 = __float2bfloat16(a1 - __bfloat162float(h1));
        __nv_bfloat16 h2 = __float2bfloat16(a2);
        __nv_bfloat16 l2 = __float2bfloat16(a2 - __bfloat162float(h2));
        g_Abf[0ULL*262144 + v*512 + w] = h1;
        g_Abf[1ULL*262144 + v*512 + w] = l1;
        g_Abf[2ULL*262144 + v*512 + w] = h2;
        g_Abf[3ULL*262144 + v*512 + w] = l2;
    }
}

// ---------------------------------------------------------------------------
// prep: pad inception weights to k=7 (windows end at l+6), build Horner W'_j,
// split everything to bf16 hi/lo in MMA-friendly layouts.
// ---------------------------------------------------------------------------
__global__ void k_prep(const float* i1w0,const float* i1b0,const float* i1w1,const float* i1b1,
                       const float* i1w2,const float* i1b2,const float* i1w3,const float* i1b3,
                       const float* i2w0,const float* i2b0,const float* i2w1,const float* i2b1,
                       const float* i2w2,const float* i2b2,const float* i2w3,const float* i2b3,
                       const float* m1w,const float* m1b,const float* m2w,const float* m2b){
    int g0 = blockIdx.x*256 + threadIdx.x, gstr = gridDim.x*256;
    const float* WS[8] = {i1w0,i1w1,i1w2,i1w3,i2w0,i2w1,i2w2,i2w3};
    const float* BS[8] = {i1b0,i1b1,i1b2,i1b3,i2b0,i2b1,i2b2,i2b3};
    const int KERN[4] = {2,3,6,7};

    // W7: [o][kd], kd = c*7 + tau
    for (int idx = g0; idx < 128*448; idx += gstr){
        int o = idx / 448, kd = idx - o*448;
        int c = kd / 7, tau = kd - c*7;
        int br = o >> 6, j = (o >> 4) & 3, oc = o & 15;
        int k = KERN[j];
        int t = tau - (7 - k);
        float v = (t >= 0) ? WS[br*4 + j][(oc*64 + c)*k + t] : 0.f;
        __nv_bfloat16 h = __float2bfloat16(v);
        g_W7h[idx] = h;
        g_W7l[idx] = __float2bfloat16(v - __bfloat162float(h));
    }
    for (int idx = g0; idx < 128; idx += gstr){
        int br = idx >> 6, j = (idx >> 4) & 3, oc = idx & 15;
        g_b7[idx] = BS[br*4 + j][oc];
    }
    for (int idx = g0; idx < 64; idx += gstr)
        g_bias[idx] = m1b[idx] + m2b[idx];

    const float COEF[5][5] = {
        {1.f, 1.f,      1.f,      1.f,      1.f     },
        {0.f, 1.f/3.f,  2.f/3.f,  1.f,      1.f     },
        {0.f, 0.f,      1.f/3.f,  1.f/3.f,  0.5f    },
        {0.f, 0.f,      0.f,      1.f/3.f,  1.f/6.f },
        {0.f, 0.f,      0.f,      0.f,      1.f/24.f}};
    // Wq bf16 stored [m][out=c][in=cp] so MMA A-fragment rows are outputs.
    for (int idx = g0; idx < 10*4096; idx += gstr){
        int m = idx >> 12, cp = (idx >> 6) & 63, c = idx & 63;
        int j = m % 5;
        const float* mw = (m < 5) ? m1w : m2w;
        float s = 0.f;
#pragma unroll
        for (int g = 0; g < 5; ++g)
            s += COEF[j][g] * mw[c*320 + g*64 + cp];
        __nv_bfloat16 h = __float2bfloat16(s);
        int widx = (m << 12) + (c << 6) + cp;   // [m][out][in]
        g_Wqh[widx] = h;
        g_Wql[widx] = __float2bfloat16(s - __bfloat162float(h));
    }
}

// ---------------------------------------------------------------------------
// FUSED inception + gate + qgen, all tensor-core (mma.sync split-bf16).
// ---------------------------------------------------------------------------
__global__ __launch_bounds__(128) void k_fused(const float* __restrict__ x){
    __shared__ __align__(16) char sm[38912];
    // stage-1 overlays
    __nv_bfloat16* sAh = (__nv_bfloat16*)(sm);            // [128][40]
    __nv_bfloat16* sAl = (__nv_bfloat16*)(sm + 10240);    // [128][40]
    __nv_bfloat16* sBh = (__nv_bfloat16*)(sm + 20480);    // [32][72]
    __nv_bfloat16* sBl = (__nv_bfloat16*)(sm + 25088);    // [32][72]
    // gate / stage-2 overlays
    float*         sG  = (float*)(sm);                    // [64][72] fp32
    __nv_bfloat16* sWh = (__nv_bfloat16*)(sm);            // [64][72]
    __nv_bfloat16* sWl = (__nv_bfloat16*)(sm + 9216);     // [64][72]
    __nv_bfloat16* sHh = (__nv_bfloat16*)(sm + 20480);    // [64][72]
    __nv_bfloat16* sHl = (__nv_bfloat16*)(sm + 29696);    // [64][72]

    int bn = blockIdx.x;
    int b = bn >> 9, n = bn & 511;
    int tid = threadIdx.x, lane = tid & 31, wid = tid >> 5;
    const float* xb = x + (u64)b*64*32768 + (u64)n*64;   // channel stride 512*64

    u32 uAh = smem_u32(sAh), uAl = smem_u32(sAl);
    u32 uBh = smem_u32(sBh), uBl = smem_u32(sBl);
    u32 uWh = smem_u32(sWh), uWl = smem_u32(sWl);
    u32 uHh = smem_u32(sHh), uHl = smem_u32(sHl);

    float acc[2][8][4];
#pragma unroll
    for (int m = 0; m < 2; ++m)
#pragma unroll
        for (int j = 0; j < 8; ++j)
#pragma unroll
            for (int e = 0; e < 4; ++e) acc[m][j][e] = 0.f;

    // ---------------- stage 1: inception GEMM (K = 448, 14 chunks of 32) ----
    for (int kc = 0; kc < 14; ++kc){
        int w0 = kc*32;
#pragma unroll
        for (int i = 0; i < 4; ++i){
            int idx = i*128 + tid;
            int row = idx >> 2, seg = idx & 3;
            *(uint4*)(sAh + row*40 + seg*8) = *(const uint4*)(g_W7h + row*448 + w0 + seg*8);
            *(uint4*)(sAl + row*40 + seg*8) = *(const uint4*)(g_W7l + row*448 + w0 + seg*8);
        }
        // B: im2col rows kd = w0+row, split fp32 -> bf16 hi/lo
#pragma unroll
        for (int i = 0; i < 8; ++i){
            int idx = i*128 + tid;          // (row, lpair): 32 x 32
            int row = idx >> 5, lp = idx & 31, l = lp*2;
            int kd = w0 + row;
            int c = kd / 7, tau = kd - c*7;
            int t = l + tau;
            float v0 = (t < 64) ? xb[(u64)c*32768 + t] : 0.f;
            float v1 = (t + 1 < 64) ? xb[(u64)c*32768 + t + 1] : 0.f;
            u32 h, lo; split2(v0, v1, h, lo);
            *(u32*)(sBh + row*72 + l) = h;
            *(u32*)(sBl + row*72 + l) = lo;
        }
        __syncthreads();
#pragma unroll
        for (int ks = 0; ks < 32; ks += 16){
            u32 ah[2][4], al[2][4];
            int arow = lane & 15, acol = ks + (lane >> 4)*8;
#pragma unroll
            for (int m = 0; m < 2; ++m){
                u32 ao = (u32)((wid*32 + m*16 + arow)*40 + acol)*2;
                ldmA(ah[m], uAh + ao);
                ldmA(al[m], uAl + ao);
            }
            int brow = ks + (lane & 15), bcol = (lane >> 4)*8;
#pragma unroll
            for (int g = 0; g < 4; ++g){
                u32 bh[4], bl[4];
                u32 bo = (u32)(brow*72 + g*16 + bcol)*2;
                ldmBT(bh, uBh + bo);
                ldmBT(bl, uBl + bo);
#pragma unroll
                for (int m = 0; m < 2; ++m){
#pragma unroll
                    for (int h = 0; h < 2; ++h){
                        float* c = acc[m][g*2 + h];
                        mma16816(c, ah[m], bh[2*h], bh[2*h+1]);
                        mma16816(c, ah[m], bl[2*h], bl[2*h+1]);
                        mma16816(c, al[m], bh[2*h], bh[2*h+1]);
                    }
                }
            }
        }
        __syncthreads();
    }

    // ---------------- gate: h = tanh(filt) * sigmoid(gate) ------------------
    int lbase = (lane & 3)*2, rbase = lane >> 2;
    if (wid >= 2){   // gate rows: o = 64..127 -> write sigmoid to sG
#pragma unroll
        for (int m = 0; m < 2; ++m){
            int o = wid*32 + m*16 + rbase;
#pragma unroll
            for (int jj = 0; jj < 8; ++jj){
                int l = jj*8 + lbase;
                float* c = acc[m][jj];
                float b0 = g_b7[o], b1 = g_b7[o + 8];
                float2 g0, g1;
                g0.x = 1.f/(1.f + expf(-(c[0] + b0)));
                g0.y = 1.f/(1.f + expf(-(c[1] + b0)));
                g1.x = 1.f/(1.f + expf(-(c[2] + b1)));
                g1.y = 1.f/(1.f + expf(-(c[3] + b1)));
                *(float2*)(sG + (o - 64)*72 + l) = g0;
                *(float2*)(sG + (o - 64 + 8)*72 + l) = g1;
            }
        }
    }
    __syncthreads();
    if (wid < 2){    // filt rows: o = c = 0..63 -> h split to sHh/sHl
#pragma unroll
        for (int m = 0; m < 2; ++m){
            int c0 = wid*32 + m*16 + rbase;
#pragma unroll
            for (int jj = 0; jj < 8; ++jj){
                int l = jj*8 + lbase;
                float* c = acc[m][jj];
                float b0 = g_b7[c0], b1 = g_b7[c0 + 8];
                float2 ga = *(const float2*)(sG + c0*72 + l);
                float2 gb = *(const float2*)(sG + (c0 + 8)*72 + l);
                float h0 = tanhf(c[0] + b0) * ga.x;
                float h1 = tanhf(c[1] + b0) * ga.y;
                float h2 = tanhf(c[2] + b1) * gb.x;
                float h3 = tanhf(c[3] + b1) * gb.y;
                u32 ph0, pl0, ph1, pl1;
                split2(h0, h1, ph0, pl0);
                split2(h2, h3, ph1, pl1);
                *(u32*)(sHh + c0*72 + l) = ph0;
                *(u32*)(sHl + c0*72 + l) = pl0;
                *(u32*)(sHh + (c0 + 8)*72 + l) = ph1;
                *(u32*)(sHl + (c0 + 8)*72 + l) = pl1;
            }
        }
    }

    // ---------------- stage 2: q_m = W'_m @ h, m = 0..9 ---------------------
    for (int m = 0; m < 10; ++m){
        __syncthreads();   // sH visible (first iter); sW safe to overwrite
#pragma unroll
        for (int i = 0; i < 4; ++i){
            int idx = i*128 + tid;
            int row = idx >> 3, seg = idx & 7;
            *(uint4*)(sWh + row*72 + seg*8) = *(const uint4*)(g_Wqh + m*4096 + row*64 + seg*8);
            *(uint4*)(sWl + row*72 + seg*8) = *(const uint4*)(g_Wql + m*4096 + row*64 + seg*8);
        }
        __syncthreads();

        float a2[8][4];
#pragma unroll
        for (int j = 0; j < 8; ++j)
#pragma unroll
            for (int e = 0; e < 4; ++e) a2[j][e] = 0.f;

#pragma unroll
        for (int ks = 0; ks < 64; ks += 16){
            u32 ah[4], al[4];
            u32 ao = (u32)((wid*16 + (lane & 15))*72 + ks + (lane >> 4)*8)*2;
            ldmA(ah, uWh + ao);
            ldmA(al, uWl + ao);
            int brow = ks + (lane & 15), bcol = (lane >> 4)*8;
#pragma unroll
            for (int g = 0; g < 4; ++g){
                u32 bh[4], bl[4];
                u32 bo = (u32)(brow*72 + g*16 + bcol)*2;
                ldmBT(bh, uHh + bo);
                ldmBT(bl, uHl + bo);
#pragma unroll
                for (int h = 0; h < 2; ++h){
                    float* c = a2[g*2 + h];
                    mma16816(c, ah, bh[2*h], bh[2*h+1]);
                    mma16816(c, ah, bl[2*h], bl[2*h+1]);
                    mma16816(c, al, bh[2*h], bh[2*h+1]);
                }
            }
        }

        // epilogue for q_m
        int cp = wid*16 + rbase;
        u64 eoff0 = ((u64)(b*64 + cp)*512 + n)*64;
        u64 eoff1 = ((u64)(b*64 + cp + 8)*512 + n)*64;
        if (m == 4 || m == 9){
            __nv_bfloat16* wh = g_bf + (u64)(m == 4 ? 0 : 6)*BUFSZ;
            __nv_bfloat16* wl = wh + BUFSZ;
#pragma unroll
            for (int jj = 0; jj < 8; ++jj){
                int l = jj*8 + lbase;
                float* c = a2[jj];
                u32 h0, l0, h1, l1;
                split2(c[0], c[1], h0, l0);
                split2(c[2], c[3], h1, l1);
                *(u32*)(wh + eoff0 + l) = h0;
                *(u32*)(wl + eoff0 + l) = l0;
                *(u32*)(wh + eoff1 + l) = h1;
                *(u32*)(wl + eoff1 + l) = l1;
            }
        } else {
            float* dst = g_pool + (u64)m*BUFSZ;
#pragma unroll
            for (int jj = 0; jj < 8; ++jj){
                int l = jj*8 + lbase;
                float* c = a2[jj];
                *(float2*)(dst + eoff0 + l) = make_float2(c[0], c[1]);
                *(float2*)(dst + eoff1 + l) = make_float2(c[2], c[3]);
            }
        }
    }
}

// ---------------------------------------------------------------------------
// tensor-core (mma.sync) Horner node step: r' = q + (M - I) @ r
// 256 threads, tile 128v x 128l (two bc per CTA), 2-stage cp.async pipeline.
// Stage layout (37888B): [Ah 10240][Al 10240][Bh 8704][Bl 8704]
//   A: 128 rows x 40-col pitch; B: 32 k-rows x 136-col pitch (l 0..127).
// Warp (wy = wid&3, wx = wid>>2): rows wy*32..+31, cols wx*64..+63.
// blockIdx.z selects branch: asel+=z, qid+=5z, bslot+=6z, wslot+=6z.
// MODE 0: write r' as bf16 hi/lo; MODE 1: fp32 -> ACC; MODE 2: final output.
// ---------------------------------------------------------------------------
#define NODE_SST 37888
#define NODE_SMEM (2*NODE_SST)

__device__ __forceinline__ void node_prefetch(
    u32 sb, const __nv_bfloat16* Ah, const __nv_bfloat16* Al,
    const __nv_bfloat16* Bh0, const __nv_bfloat16* Bl0,
    int w0, int v0c, int tid){
    // A: 128 rows x 4 segs (hi + lo)
#pragma unroll
    for (int i = 0; i < 2; ++i){
        int idx = i*256 + tid;              // 0..511
        int row = idx >> 2, seg = idx & 3;
        u64 goff = (u64)(v0c + row)*512 + w0 + seg*8;
        cpa16(sb + row*80 + seg*16, Ah + goff);
        cpa16(sb + 10240 + row*80 + seg*16, Al + goff);
    }
    // B: 32 k-rows x 16 segs (segs 0..7 -> bc0, 8..15 -> bc1)
#pragma unroll
    for (int i = 0; i < 2; ++i){
        int idx = i*256 + tid;              // 0..511
        int row = idx >> 4, seg = idx & 15;
        u64 goff = (u64)(seg >> 3)*32768 + (u64)(w0 + row)*64 + (seg & 7)*8;
        cpa16(sb + 20480 + row*272 + seg*16, Bh0 + goff);
        cpa16(sb + 29184 + row*272 + seg*16, Bl0 + goff);
    }
}

template<int MODE>
__global__ __launch_bounds__(256, 2)
void k_node_mma(int asel, int qid, int bslot, int wslot, float* __restrict__ outp){
    extern __shared__ __align__(16) char smn[];
    u32 base = smem_u32(smn);

    int z = blockIdx.z;
    asel += z; qid += 5*z; bslot += 6*z; wslot += 6*z;

    int tid = threadIdx.x, lane = tid & 31, wid = tid >> 5;
    int wy = wid & 3, wx = wid >> 2;
    int bc0 = blockIdx.x*2, v0c = blockIdx.y << 7;

    const __nv_bfloat16* Ah = g_Abf + (u64)(asel*2)*262144;
    const __nv_bfloat16* Al = Ah + 262144;
    const __nv_bfloat16* Bh0 = g_bf + (u64)bslot*BUFSZ + (u64)bc0*32768;
    const __nv_bfloat16* Bl0 = g_bf + (u64)(bslot+1)*BUFSZ + (u64)bc0*32768;

    float acc[2][8][4];
#pragma unroll
    for (int m = 0; m < 2; ++m)
#pragma unroll
        for (int j = 0; j < 8; ++j)
#pragma unroll
            for (int e = 0; e < 4; ++e) acc[m][j][e] = 0.f;

    // prologue: prefetch chunk 0
    node_prefetch(base, Ah, Al, Bh0, Bl0, 0, v0c, tid);
    cpa_commit();

    for (int kc = 0; kc < 16; ++kc){
        if (kc < 15){
            node_prefetch(base + ((kc+1)&1)*NODE_SST, Ah, Al, Bh0, Bl0,
                          (kc+1)*32, v0c, tid);
            cpa_commit();
            cpa_wait<1>();
        } else {
            cpa_wait<0>();
        }
        __syncthreads();

        u32 sb = base + (kc&1)*NODE_SST;
        u32 uAh = sb, uAl = sb + 10240, uBh = sb + 20480, uBl = sb + 29184;
#pragma unroll
        for (int ks = 0; ks < 32; ks += 16){
            u32 ah[2][4], al[2][4];
            int arow = lane & 15, acol = ks + (lane >> 4)*8;
#pragma unroll
            for (int m = 0; m < 2; ++m){
                u32 ao = (u32)((wy*32 + m*16 + arow)*40 + acol)*2;
                ldmA(ah[m], uAh + ao);
                ldmA(al[m], uAl + ao);
            }
            int brow = ks + (lane & 15), bcol = (lane >> 4)*8;
#pragma unroll
            for (int g = 0; g < 4; ++g){
                u32 bh[4], bl[4];
                u32 bo = (u32)(brow*136 + (wx*4 + g)*16 + bcol)*2;
                ldmBT(bh, uBh + bo);
                ldmBT(bl, uBl + bo);
#pragma unroll
                for (int m = 0; m < 2; ++m){
#pragma unroll
                    for (int h = 0; h < 2; ++h){
                        float* c = acc[m][g*2 + h];
                        mma16816(c, ah[m], bh[2*h], bh[2*h+1]);
                        mma16816(c, ah[m], bl[2*h], bl[2*h+1]);
                        mma16816(c, al[m], bh[2*h], bh[2*h+1]);
                    }
                }
            }
        }
        __syncthreads();   // all reads of stage kc done before it is overwritten
    }

    int lbase = (lane & 3)*2, rbase = lane >> 2;
#pragma unroll
    for (int m = 0; m < 2; ++m){
        int v = v0c + wy*32 + m*16 + rbase;
#pragma unroll
        for (int jj = 0; jj < 8; ++jj){
            int nloc = wx*64 + jj*8 + lbase;       // 0..127
            int bcl = bc0 + (nloc >> 6);
            int l = nloc & 63;
            float* c = acc[m][jj];
            const float* qp = g_pool + (u64)qid*BUFSZ + (u64)bcl*32768;
            float2 q0 = *(const float2*)(qp + (u64)v*64 + l);
            float2 q1 = *(const float2*)(qp + (u64)(v+8)*64 + l);
            float a0 = c[0] + q0.x, a1 = c[1] + q0.y;
            float a2 = c[2] + q1.x, a3 = c[3] + q1.y;
            if (MODE == 0){
                __nv_bfloat16* wh = g_bf + (u64)wslot*BUFSZ + (u64)bcl*32768;
                __nv_bfloat16* wl = wh + BUFSZ;
                u32 h0, l0, h1, l1;
                split2(a0, a1, h0, l0);
                split2(a2, a3, h1, l1);
                *(u32*)(wh + (u64)v*64 + l) = h0;
                *(u32*)(wl + (u64)v*64 + l) = l0;
                *(u32*)(wh + (u64)(v+8)*64 + l) = h1;
                *(u32*)(wl + (u64)(v+8)*64 + l) = l1;
            } else if (MODE == 1){
                float* op = g_pool + 12ULL*BUFSZ + (u64)bcl*32768;
                *(float2*)(op + (u64)v*64 + l) = make_float2(a0, a1);
                *(float2*)(op + (u64)(v+8)*64 + l) = make_float2(a2, a3);
            } else {
                const float* ap = g_pool + 12ULL*BUFSZ + (u64)bcl*32768;
                float bia = g_bias[bcl & 63];
                float* op = outp + (u64)bcl*32768;
                a0 += ap[(u64)v*64 + l] + bia;
                a1 += ap[(u64)v*64 + l + 1] + bia;
                a2 += ap[(u64)(v+8)*64 + l] + bia;
                a3 += ap[(u64)(v+8)*64 + l + 1] + bia;
                if (l < 58)     op[(u64)v*64 + l + 6]       = a0;
                if (l + 1 < 58) op[(u64)v*64 + l + 7]       = a1;
                if (l < 58)     op[(u64)(v+8)*64 + l + 6]   = a2;
                if (l + 1 < 58) op[(u64)(v+8)*64 + l + 7]   = a3;
            }
        }
    }
}

__global__ void k_zeropad(float* __restrict__ outp){
    int i = blockIdx.x*256 + threadIdx.x;
    if (i < 8*64*512*6){
        int row = i / 6, t = i - row*6;
        outp[(u64)row*64 + t] = 0.f;
    }
}

// ---------------------------------------------------------------------------
extern "C" void kernel_launch(void* const* d_in, const int* in_sizes, int n_in,
                              void* d_out, int out_size){
    (void)in_sizes; (void)n_in; (void)out_size;
    const float* x   = (const float*)d_in[0];
    const float* adj = (const float*)d_in[1];
    float* out = (float*)d_out;

    // allow >48KB dynamic smem for the node kernels (idempotent)
    cudaFuncSetAttribute(k_node_mma<0>, cudaFuncAttributeMaxDynamicSharedMemorySize, NODE_SMEM);
    cudaFuncSetAttribute(k_node_mma<1>, cudaFuncAttributeMaxDynamicSharedMemorySize, NODE_SMEM);
    cudaFuncSetAttribute(k_node_mma<2>, cudaFuncAttributeMaxDynamicSharedMemorySize, NODE_SMEM);

    k_deg  <<<512, 256>>>(adj);
    k_norm <<<512, 256>>>(adj);
    k_prepA<<<512, 256>>>();
    k_prep<<<64, 256>>>(
        (const float*)d_in[ 2], (const float*)d_in[ 3], (const float*)d_in[ 4], (const float*)d_in[ 5],
        (const float*)d_in[ 6], (const float*)d_in[ 7], (const float*)d_in[ 8], (const float*)d_in[ 9],
        (const float*)d_in[10], (const float*)d_in[11], (const float*)d_in[12], (const float*)d_in[13],
        (const float*)d_in[14], (const float*)d_in[15], (const float*)d_in[16], (const float*)d_in[17],
        (const float*)d_in[18], (const float*)d_in[19], (const float*)d_in[20], (const float*)d_in[21]);

    k_fused<<<4096, 128>>>(x);

    // Horner: branch0 seed slot 0 (q4), branch1 seed slot 6 (q9);
    // merged launches run both branches via gridDim.z = 2.
    dim3 ng3(256, 4, 2);
    k_node_mma<0><<<ng3, 256, NODE_SMEM>>>(0, 3, 0, 2, nullptr);   // step 0
    k_node_mma<0><<<ng3, 256, NODE_SMEM>>>(0, 2, 2, 4, nullptr);   // step 1
    k_node_mma<0><<<ng3, 256, NODE_SMEM>>>(0, 1, 4, 2, nullptr);   // step 2
    dim3 ng(256, 4, 1);
    k_node_mma<1><<<ng, 256, NODE_SMEM>>>(0, 0, 2, 0, nullptr);    // b0 final -> ACC
    k_node_mma<2><<<ng, 256, NODE_SMEM>>>(1, 5, 8, 0, out);        // b1 final -> out

    k_zeropad<<<6144, 256>>>(out);
}

// round 11
// speedup vs baseline: 2.8637x; 1.1382x over previous
#include <cuda_runtime.h>
#include <cuda_bf16.h>

typedef unsigned long long u64;
typedef unsigned int u32;

// ---------------------------------------------------------------------------
// Shapes: B=8, C=64, N=512, T=64, valid L=58 (stored padded to 64).
// fp32 pool: q0..q9 (ids 0-9; 4 and 9 unused as fp32), ACC=12.
// bf16 pool slots (BUFSZ each):
//   0/1 seed1(q4) hi/lo, 2/3 & 4/5 branch0 ping-pong,
//   6/7 seed2(q9) hi/lo, 8/9 & 10/11 branch1 ping-pong.
// Node step: r' = q + d∘r + A'·r  with d = diag(M)-1 (fp32, epilogue) and
// A' = M - diag(M) (tiny entries ~4e-3, plain bf16, 2 MMA products).
// ---------------------------------------------------------------------------
#define BUFSZ (8ULL*64ULL*512ULL*64ULL)

__device__ float g_pool[13ULL*BUFSZ];
__device__ __nv_bfloat16 g_bf[12ULL*BUFSZ];
__device__ __nv_bfloat16 g_Abf[4ULL*512*512];  // slots 0,2 used: [asel*2][v][w] of A'
__device__ float g_dA[2*512];                  // diag(M)-1 per branch

__device__ float g_An [512*512];   // [w][v] = M1[v][w]
__device__ float g_AnT[512*512];   // [w][v] = M2[v][w]
__device__ float g_rd1[512], g_rd2[512];
__device__ __nv_bfloat16 g_W7h[128*448];   // [o][kd] hi
__device__ __nv_bfloat16 g_W7l[128*448];   // [o][kd] lo
__device__ float g_b7[128];
__device__ __nv_bfloat16 g_Wqh[10*64*64];  // [m][out][in] hi  (MMA A-row = out)
__device__ __nv_bfloat16 g_Wql[10*64*64];  // [m][out][in] lo
__device__ float g_bias[64];

// ---------------------------------------------------------------------------
// helpers
// ---------------------------------------------------------------------------
__device__ __forceinline__ u32 smem_u32(const void* p){
    u32 a;
    asm("{ .reg .u64 t; cvta.to.shared.u64 t, %1; cvt.u32.u64 %0, t; }" : "=r"(a) : "l"(p));
    return a;
}
// split a pair of fp32 into packed bf16 hi / bf16 lo
__device__ __forceinline__ void split2(float a0, float a1, u32& hi, u32& lo){
    __nv_bfloat16 h0 = __float2bfloat16(a0);
    __nv_bfloat16 h1 = __float2bfloat16(a1);
    float r0 = a0 - __bfloat162float(h0);
    float r1 = a1 - __bfloat162float(h1);
    union { __nv_bfloat162 v; u32 u; } ch, cl;
    ch.v = __halves2bfloat162(h0, h1);
    cl.v = __halves2bfloat162(__float2bfloat16(r0), __float2bfloat16(r1));
    hi = ch.u; lo = cl.u;
}
__device__ __forceinline__ float2 bf2f2(u32 u){
    union { u32 u; __nv_bfloat162 v; } c; c.u = u;
    return __bfloat1622float2(c.v);
}

// ---------------------------------------------------------------------------
// mma.sync / ldmatrix / cp.async wrappers (baseline PTX, legal on compute_103)
// ---------------------------------------------------------------------------
__device__ __forceinline__ void mma16816(float* c, const u32* a, u32 b0, u32 b1){
    asm volatile(
        "mma.sync.aligned.m16n8k16.row.col.f32.bf16.bf16.f32 "
        "{%0,%1,%2,%3}, {%4,%5,%6,%7}, {%8,%9}, {%0,%1,%2,%3};"
        : "+f"(c[0]), "+f"(c[1]), "+f"(c[2]), "+f"(c[3])
        : "r"(a[0]), "r"(a[1]), "r"(a[2]), "r"(a[3]), "r"(b0), "r"(b1));
}
__device__ __forceinline__ void ldmA(u32* r, u32 addr){
    asm volatile("ldmatrix.sync.aligned.m8n8.x4.shared.b16 {%0,%1,%2,%3}, [%4];"
        : "=r"(r[0]), "=r"(r[1]), "=r"(r[2]), "=r"(r[3]) : "r"(addr));
}
__device__ __forceinline__ void ldmBT(u32* r, u32 addr){
    asm volatile("ldmatrix.sync.aligned.m8n8.x4.trans.shared.b16 {%0,%1,%2,%3}, [%4];"
        : "=r"(r[0]), "=r"(r[1]), "=r"(r[2]), "=r"(r[3]) : "r"(addr));
}
__device__ __forceinline__ void cpa16(u32 dst, const void* src){
    asm volatile("cp.async.cg.shared.global [%0], [%1], 16;" :: "r"(dst), "l"(src));
}
__device__ __forceinline__ void cpa_commit(){
    asm volatile("cp.async.commit_group;" ::: "memory");
}
template<int N>
__device__ __forceinline__ void cpa_wait(){
    asm volatile("cp.async.wait_group %0;" :: "n"(N) : "memory");
}

// ---------------------------------------------------------------------------
// degrees + normalized adjacencies
// ---------------------------------------------------------------------------
__global__ void k_deg(const float* __restrict__ adj){
    int v = blockIdx.x, tid = threadIdx.x;
    float s1 = 0.f, s2 = 0.f;
    for (int w = tid; w < 512; w += 256){
        s1 += adj[v*512 + w];
        s2 += adj[w*512 + v];
    }
    __shared__ float r1[256], r2[256];
    r1[tid] = s1; r2[tid] = s2;
    __syncthreads();
    for (int s = 128; s > 0; s >>= 1){
        if (tid < s){ r1[tid] += r1[tid+s]; r2[tid] += r2[tid+s]; }
        __syncthreads();
    }
    if (tid == 0){
        g_rd1[v] = rsqrtf(r1[0] + 1.f);
        g_rd2[v] = rsqrtf(r2[0] + 1.f);
    }
}

__global__ void k_norm(const float* __restrict__ adj){
    int w = blockIdx.x;
    float dw1 = g_rd1[w], dw2 = g_rd2[w];
    for (int v = threadIdx.x; v < 512; v += 256){
        float e = (v == w) ? 1.f : 0.f;
        g_An [w*512 + v] = g_rd1[v] * (adj[v*512 + w] + e) * dw1;
        g_AnT[w*512 + v] = g_rd2[v] * (adj[w*512 + v] + e) * dw2;
    }
}

// A' = M - diag(M) as plain bf16 [v][w]; d = diag(M) - 1 in fp32.
__global__ void k_prepA(){
    int v = blockIdx.x;
    for (int w = threadIdx.x; w < 512; w += 256){
        float a1 = g_An [w*512 + v];
        float a2 = g_AnT[w*512 + v];
        if (w == v){
            g_dA[v]       = a1 - 1.f;
            g_dA[512 + v] = a2 - 1.f;
            a1 = 0.f; a2 = 0.f;
        }
        g_Abf[0ULL*262144 + v*512 + w] = __float2bfloat16(a1);
        g_Abf[2ULL*262144 + v*512 + w] = __float2bfloat16(a2);
    }
}

// ---------------------------------------------------------------------------
// prep: pad inception weights to k=7 (windows end at l+6), build Horner W'_j,
// split everything to bf16 hi/lo in MMA-friendly layouts.
// ---------------------------------------------------------------------------
__global__ void k_prep(const float* i1w0,const float* i1b0,const float* i1w1,const float* i1b1,
                       const float* i1w2,const float* i1b2,const float* i1w3,const float* i1b3,
                       const float* i2w0,const float* i2b0,const float* i2w1,const float* i2b1,
                       const float* i2w2,const float* i2b2,const float* i2w3,const float* i2b3,
                       const float* m1w,const float* m1b,const float* m2w,const float* m2b){
    int g0 = blockIdx.x*256 + threadIdx.x, gstr = gridDim.x*256;
    const float* WS[8] = {i1w0,i1w1,i1w2,i1w3,i2w0,i2w1,i2w2,i2w3};
    const float* BS[8] = {i1b0,i1b1,i1b2,i1b3,i2b0,i2b1,i2b2,i2b3};
    const int KERN[4] = {2,3,6,7};

    // W7: [o][kd], kd = c*7 + tau
    for (int idx = g0; idx < 128*448; idx += gstr){
        int o = idx / 448, kd = idx - o*448;
        int c = kd / 7, tau = kd - c*7;
        int br = o >> 6, j = (o >> 4) & 3, oc = o & 15;
        int k = KERN[j];
        int t = tau - (7 - k);
        float v = (t >= 0) ? WS[br*4 + j][(oc*64 + c)*k + t] : 0.f;
        __nv_bfloat16 h = __float2bfloat16(v);
        g_W7h[idx] = h;
        g_W7l[idx] = __float2bfloat16(v - __bfloat162float(h));
    }
    for (int idx = g0; idx < 128; idx += gstr){
        int br = idx >> 6, j = (idx >> 4) & 3, oc = idx & 15;
        g_b7[idx] = BS[br*4 + j][oc];
    }
    for (int idx = g0; idx < 64; idx += gstr)
        g_bias[idx] = m1b[idx] + m2b[idx];

    const float COEF[5][5] = {
        {1.f, 1.f,      1.f,      1.f,      1.f     },
        {0.f, 1.f/3.f,  2.f/3.f,  1.f,      1.f     },
        {0.f, 0.f,      1.f/3.f,  1.f/3.f,  0.5f    },
        {0.f, 0.f,      0.f,      1.f/3.f,  1.f/6.f },
        {0.f, 0.f,      0.f,      0.f,      1.f/24.f}};
    // Wq bf16 stored [m][out=c][in=cp] so MMA A-fragment rows are outputs.
    for (int idx = g0; idx < 10*4096; idx += gstr){
        int m = idx >> 12, cp = (idx >> 6) & 63, c = idx & 63;
        int j = m % 5;
        const float* mw = (m < 5) ? m1w : m2w;
        float s = 0.f;
#pragma unroll
        for (int g = 0; g < 5; ++g)
            s += COEF[j][g] * mw[c*320 + g*64 + cp];
        __nv_bfloat16 h = __float2bfloat16(s);
        int widx = (m << 12) + (c << 6) + cp;   // [m][out][in]
        g_Wqh[widx] = h;
        g_Wql[widx] = __float2bfloat16(s - __bfloat162float(h));
    }
}

// ---------------------------------------------------------------------------
// FUSED inception + gate + qgen, all tensor-core (mma.sync split-bf16).
// ---------------------------------------------------------------------------
__global__ __launch_bounds__(128) void k_fused(const float* __restrict__ x){
    __shared__ __align__(16) char sm[38912];
    // stage-1 overlays
    __nv_bfloat16* sAh = (__nv_bfloat16*)(sm);            // [128][40]
    __nv_bfloat16* sAl = (__nv_bfloat16*)(sm + 10240);    // [128][40]
    __nv_bfloat16* sBh = (__nv_bfloat16*)(sm + 20480);    // [32][72]
    __nv_bfloat16* sBl = (__nv_bfloat16*)(sm + 25088);    // [32][72]
    // gate / stage-2 overlays
    float*         sG  = (float*)(sm);                    // [64][72] fp32
    __nv_bfloat16* sWh = (__nv_bfloat16*)(sm);            // [64][72]
    __nv_bfloat16* sWl = (__nv_bfloat16*)(sm + 9216);     // [64][72]
    __nv_bfloat16* sHh = (__nv_bfloat16*)(sm + 20480);    // [64][72]
    __nv_bfloat16* sHl = (__nv_bfloat16*)(sm + 29696);    // [64][72]

    int bn = blockIdx.x;
    int b = bn >> 9, n = bn & 511;
    int tid = threadIdx.x, lane = tid & 31, wid = tid >> 5;
    const float* xb = x + (u64)b*64*32768 + (u64)n*64;   // channel stride 512*64

    u32 uAh = smem_u32(sAh), uAl = smem_u32(sAl);
    u32 uBh = smem_u32(sBh), uBl = smem_u32(sBl);
    u32 uWh = smem_u32(sWh), uWl = smem_u32(sWl);
    u32 uHh = smem_u32(sHh), uHl = smem_u32(sHl);

    float acc[2][8][4];
#pragma unroll
    for (int m = 0; m < 2; ++m)
#pragma unroll
        for (int j = 0; j < 8; ++j)
#pragma unroll
            for (int e = 0; e < 4; ++e) acc[m][j][e] = 0.f;

    // ---------------- stage 1: inception GEMM (K = 448, 14 chunks of 32) ----
    for (int kc = 0; kc < 14; ++kc){
        int w0 = kc*32;
#pragma unroll
        for (int i = 0; i < 4; ++i){
            int idx = i*128 + tid;
            int row = idx >> 2, seg = idx & 3;
            *(uint4*)(sAh + row*40 + seg*8) = *(const uint4*)(g_W7h + row*448 + w0 + seg*8);
            *(uint4*)(sAl + row*40 + seg*8) = *(const uint4*)(g_W7l + row*448 + w0 + seg*8);
        }
        // B: im2col rows kd = w0+row, split fp32 -> bf16 hi/lo
#pragma unroll
        for (int i = 0; i < 8; ++i){
            int idx = i*128 + tid;          // (row, lpair): 32 x 32
            int row = idx >> 5, lp = idx & 31, l = lp*2;
            int kd = w0 + row;
            int c = kd / 7, tau = kd - c*7;
            int t = l + tau;
            float v0 = (t < 64) ? xb[(u64)c*32768 + t] : 0.f;
            float v1 = (t + 1 < 64) ? xb[(u64)c*32768 + t + 1] : 0.f;
            u32 h, lo; split2(v0, v1, h, lo);
            *(u32*)(sBh + row*72 + l) = h;
            *(u32*)(sBl + row*72 + l) = lo;
        }
        __syncthreads();
#pragma unroll
        for (int ks = 0; ks < 32; ks += 16){
            u32 ah[2][4], al[2][4];
            int arow = lane & 15, acol = ks + (lane >> 4)*8;
#pragma unroll
            for (int m = 0; m < 2; ++m){
                u32 ao = (u32)((wid*32 + m*16 + arow)*40 + acol)*2;
                ldmA(ah[m], uAh + ao);
                ldmA(al[m], uAl + ao);
            }
            int brow = ks + (lane & 15), bcol = (lane >> 4)*8;
#pragma unroll
            for (int g = 0; g < 4; ++g){
                u32 bh[4], bl[4];
                u32 bo = (u32)(brow*72 + g*16 + bcol)*2;
                ldmBT(bh, uBh + bo);
                ldmBT(bl, uBl + bo);
#pragma unroll
                for (int m = 0; m < 2; ++m){
#pragma unroll
                    for (int h = 0; h < 2; ++h){
                        float* c = acc[m][g*2 + h];
                        mma16816(c, ah[m], bh[2*h], bh[2*h+1]);
                        mma16816(c, ah[m], bl[2*h], bl[2*h+1]);
                        mma16816(c, al[m], bh[2*h], bh[2*h+1]);
                    }
                }
            }
        }
        __syncthreads();
    }

    // ---------------- gate: h = tanh(filt) * sigmoid(gate) ------------------
    int lbase = (lane & 3)*2, rbase = lane >> 2;
    if (wid >= 2){   // gate rows: o = 64..127 -> write sigmoid to sG
#pragma unroll
        for (int m = 0; m < 2; ++m){
            int o = wid*32 + m*16 + rbase;
#pragma unroll
            for (int jj = 0; jj < 8; ++jj){
                int l = jj*8 + lbase;
                float* c = acc[m][jj];
                float b0 = g_b7[o], b1 = g_b7[o + 8];
                float2 g0, g1;
                g0.x = 1.f/(1.f + expf(-(c[0] + b0)));
                g0.y = 1.f/(1.f + expf(-(c[1] + b0)));
                g1.x = 1.f/(1.f + expf(-(c[2] + b1)));
                g1.y = 1.f/(1.f + expf(-(c[3] + b1)));
                *(float2*)(sG + (o - 64)*72 + l) = g0;
                *(float2*)(sG + (o - 64 + 8)*72 + l) = g1;
            }
        }
    }
    __syncthreads();
    if (wid < 2){    // filt rows: o = c = 0..63 -> h split to sHh/sHl
#pragma unroll
        for (int m = 0; m < 2; ++m){
            int c0 = wid*32 + m*16 + rbase;
#pragma unroll
            for (int jj = 0; jj < 8; ++jj){
                int l = jj*8 + lbase;
                float* c = acc[m][jj];
                float b0 = g_b7[c0], b1 = g_b7[c0 + 8];
                float2 ga = *(const float2*)(sG + c0*72 + l);
                float2 gb = *(const float2*)(sG + (c0 + 8)*72 + l);
                float h0 = tanhf(c[0] + b0) * ga.x;
                float h1 = tanhf(c[1] + b0) * ga.y;
                float h2 = tanhf(c[2] + b1) * gb.x;
                float h3 = tanhf(c[3] + b1) * gb.y;
                u32 ph0, pl0, ph1, pl1;
                split2(h0, h1, ph0, pl0);
                split2(h2, h3, ph1, pl1);
                *(u32*)(sHh + c0*72 + l) = ph0;
                *(u32*)(sHl + c0*72 + l) = pl0;
                *(u32*)(sHh + (c0 + 8)*72 + l) = ph1;
                *(u32*)(sHl + (c0 + 8)*72 + l) = pl1;
            }
        }
    }

    // ---------------- stage 2: q_m = W'_m @ h, m = 0..9 ---------------------
    for (int m = 0; m < 10; ++m){
        __syncthreads();   // sH visible (first iter); sW safe to overwrite
#pragma unroll
        for (int i = 0; i < 4; ++i){
            int idx = i*128 + tid;
            int row = idx >> 3, seg = idx & 7;
            *(uint4*)(sWh + row*72 + seg*8) = *(const uint4*)(g_Wqh + m*4096 + row*64 + seg*8);
            *(uint4*)(sWl + row*72 + seg*8) = *(const uint4*)(g_Wql + m*4096 + row*64 + seg*8);
        }
        __syncthreads();

        float a2[8][4];
#pragma unroll
        for (int j = 0; j < 8; ++j)
#pragma unroll
            for (int e = 0; e < 4; ++e) a2[j][e] = 0.f;

#pragma unroll
        for (int ks = 0; ks < 64; ks += 16){
            u32 ah[4], al[4];
            u32 ao = (u32)((wid*16 + (lane & 15))*72 + ks + (lane >> 4)*8)*2;
            ldmA(ah, uWh + ao);
            ldmA(al, uWl + ao);
            int brow = ks + (lane & 15), bcol = (lane >> 4)*8;
#pragma unroll
            for (int g = 0; g < 4; ++g){
                u32 bh[4], bl[4];
                u32 bo = (u32)(brow*72 + g*16 + bcol)*2;
                ldmBT(bh, uHh + bo);
                ldmBT(bl, uHl + bo);
#pragma unroll
                for (int h = 0; h < 2; ++h){
                    float* c = a2[g*2 + h];
                    mma16816(c, ah, bh[2*h], bh[2*h+1]);
                    mma16816(c, ah, bl[2*h], bl[2*h+1]);
                    mma16816(c, al, bh[2*h], bh[2*h+1]);
                }
            }
        }

        // epilogue for q_m
        int cp = wid*16 + rbase;
        u64 eoff0 = ((u64)(b*64 + cp)*512 + n)*64;
        u64 eoff1 = ((u64)(b*64 + cp + 8)*512 + n)*64;
        if (m == 4 || m == 9){
            __nv_bfloat16* wh = g_bf + (u64)(m == 4 ? 0 : 6)*BUFSZ;
            __nv_bfloat16* wl = wh + BUFSZ;
#pragma unroll
            for (int jj = 0; jj < 8; ++jj){
                int l = jj*8 + lbase;
                float* c = a2[jj];
                u32 h0, l0, h1, l1;
                split2(c[0], c[1], h0, l0);
                split2(c[2], c[3], h1, l1);
                *(u32*)(wh + eoff0 + l) = h0;
                *(u32*)(wl + eoff0 + l) = l0;
                *(u32*)(wh + eoff1 + l) = h1;
                *(u32*)(wl + eoff1 + l) = l1;
            }
        } else {
            float* dst = g_pool + (u64)m*BUFSZ;
#pragma unroll
            for (int jj = 0; jj < 8; ++jj){
                int l = jj*8 + lbase;
                float* c = a2[jj];
                *(float2*)(dst + eoff0 + l) = make_float2(c[0], c[1]);
                *(float2*)(dst + eoff1 + l) = make_float2(c[2], c[3]);
            }
        }
    }
}

// ---------------------------------------------------------------------------
// tensor-core (mma.sync) Horner node step: r' = q + d∘r + A'·r
// A' plain bf16 (2 MMA products: A'h·Bh + A'h·Bl); diagonal exact in epilogue.
// 256 threads, tile 128v x 128l (two bc per CTA), 2-stage cp.async pipeline.
// Stage layout (27648B): [Ah 10240][Bh 8704][Bl 8704]
// Warp (wy = wid&3, wx = wid>>2): rows wy*32..+31, cols wx*64..+63.
// blockIdx.z selects branch: asel+=z, qid+=5z, bslot+=6z, wslot+=6z.
// MODE 0: write r' as bf16 hi/lo; MODE 1: fp32 -> ACC; MODE 2: final output.
// ---------------------------------------------------------------------------
#define NODE_SST 27648
#define NODE_SMEM (2*NODE_SST)

__device__ __forceinline__ void node_prefetch(
    u32 sb, const __nv_bfloat16* Ah,
    const __nv_bfloat16* Bh0, const __nv_bfloat16* Bl0,
    int w0, int v0c, int tid){
    // A: 128 rows x 4 segs (hi only)
#pragma unroll
    for (int i = 0; i < 2; ++i){
        int idx = i*256 + tid;              // 0..511
        int row = idx >> 2, seg = idx & 3;
        u64 goff = (u64)(v0c + row)*512 + w0 + seg*8;
        cpa16(sb + row*80 + seg*16, Ah + goff);
    }
    // B: 32 k-rows x 16 segs (segs 0..7 -> bc0, 8..15 -> bc1)
#pragma unroll
    for (int i = 0; i < 2; ++i){
        int idx = i*256 + tid;              // 0..511
        int row = idx >> 4, seg = idx & 15;
        u64 goff = (u64)(seg >> 3)*32768 + (u64)(w0 + row)*64 + (seg & 7)*8;
        cpa16(sb + 10240 + row*272 + seg*16, Bh0 + goff);
        cpa16(sb + 18944 + row*272 + seg*16, Bl0 + goff);
    }
}

template<int MODE>
__global__ __launch_bounds__(256, 2)
void k_node_mma(int asel, int qid, int bslot, int wslot, float* __restrict__ outp){
    extern __shared__ __align__(16) char smn[];
    u32 base = smem_u32(smn);

    int z = blockIdx.z;
    asel += z; qid += 5*z; bslot += 6*z; wslot += 6*z;

    int tid = threadIdx.x, lane = tid & 31, wid = tid >> 5;
    int wy = wid & 3, wx = wid >> 2;
    int bc0 = blockIdx.x*2, v0c = blockIdx.y << 7;

    const __nv_bfloat16* Ah = g_Abf + (u64)(asel*2)*262144;
    const __nv_bfloat16* Bh0 = g_bf + (u64)bslot*BUFSZ + (u64)bc0*32768;
    const __nv_bfloat16* Bl0 = g_bf + (u64)(bslot+1)*BUFSZ + (u64)bc0*32768;
    const float* dvec = g_dA + asel*512;

    float acc[2][8][4];
#pragma unroll
    for (int m = 0; m < 2; ++m)
#pragma unroll
        for (int j = 0; j < 8; ++j)
#pragma unroll
            for (int e = 0; e < 4; ++e) acc[m][j][e] = 0.f;

    // prologue: prefetch chunk 0
    node_prefetch(base, Ah, Bh0, Bl0, 0, v0c, tid);
    cpa_commit();

    for (int kc = 0; kc < 16; ++kc){
        if (kc < 15){
            node_prefetch(base + ((kc+1)&1)*NODE_SST, Ah, Bh0, Bl0,
                          (kc+1)*32, v0c, tid);
            cpa_commit();
            cpa_wait<1>();
        } else {
            cpa_wait<0>();
        }
        __syncthreads();

        u32 sb = base + (kc&1)*NODE_SST;
        u32 uAh = sb, uBh = sb + 10240, uBl = sb + 18944;
#pragma unroll
        for (int ks = 0; ks < 32; ks += 16){
            u32 ah[2][4];
            int arow = lane & 15, acol = ks + (lane >> 4)*8;
#pragma unroll
            for (int m = 0; m < 2; ++m){
                u32 ao = (u32)((wy*32 + m*16 + arow)*40 + acol)*2;
                ldmA(ah[m], uAh + ao);
            }
            int brow = ks + (lane & 15), bcol = (lane >> 4)*8;
#pragma unroll
            for (int g = 0; g < 4; ++g){
                u32 bh[4], bl[4];
                u32 bo = (u32)(brow*136 + (wx*4 + g)*16 + bcol)*2;
                ldmBT(bh, uBh + bo);
                ldmBT(bl, uBl + bo);
#pragma unroll
                for (int m = 0; m < 2; ++m){
#pragma unroll
                    for (int h = 0; h < 2; ++h){
                        float* c = acc[m][g*2 + h];
                        mma16816(c, ah[m], bh[2*h], bh[2*h+1]);
                        mma16816(c, ah[m], bl[2*h], bl[2*h+1]);
                    }
                }
            }
        }
        __syncthreads();   // all reads of stage kc done before it is overwritten
    }

    int lbase = (lane & 3)*2, rbase = lane >> 2;
#pragma unroll
    for (int m = 0; m < 2; ++m){
        int v = v0c + wy*32 + m*16 + rbase;
        float d0 = dvec[v], d1 = dvec[v + 8];
#pragma unroll
        for (int jj = 0; jj < 8; ++jj){
            int nloc = wx*64 + jj*8 + lbase;       // 0..127
            int bcl = bc0 + (nloc >> 6);
            int l = nloc & 63;
            float* c = acc[m][jj];
            const float* qp = g_pool + (u64)qid*BUFSZ + (u64)bcl*32768;
            float2 q0 = *(const float2*)(qp + (u64)v*64 + l);
            float2 q1 = *(const float2*)(qp + (u64)(v+8)*64 + l);
            // reconstruct r (17-bit) for the exact diagonal path
            const __nv_bfloat16* rhp = g_bf + (u64)bslot*BUFSZ + (u64)bcl*32768;
            const __nv_bfloat16* rlp = rhp + BUFSZ;
            float2 r0h = bf2f2(*(const u32*)(rhp + (u64)v*64 + l));
            float2 r0l = bf2f2(*(const u32*)(rlp + (u64)v*64 + l));
            float2 r1h = bf2f2(*(const u32*)(rhp + (u64)(v+8)*64 + l));
            float2 r1l = bf2f2(*(const u32*)(rlp + (u64)(v+8)*64 + l));
            float r00 = r0h.x + r0l.x, r01 = r0h.y + r0l.y;
            float r10 = r1h.x + r1l.x, r11 = r1h.y + r1l.y;
            float a0 = c[0] + q0.x + d0*r00;
            float a1 = c[1] + q0.y + d0*r01;
            float a2 = c[2] + q1.x + d1*r10;
            float a3 = c[3] + q1.y + d1*r11;
            if (MODE == 0){
                __nv_bfloat16* wh = g_bf + (u64)wslot*BUFSZ + (u64)bcl*32768;
                __nv_bfloat16* wl = wh + BUFSZ;
                u32 h0, l0, h1, l1;
                split2(a0, a1, h0, l0);
                split2(a2, a3, h1, l1);
                *(u32*)(wh + (u64)v*64 + l) = h0;
                *(u32*)(wl + (u64)v*64 + l) = l0;
                *(u32*)(wh + (u64)(v+8)*64 + l) = h1;
                *(u32*)(wl + (u64)(v+8)*64 + l) = l1;
            } else if (MODE == 1){
                float* op = g_pool + 12ULL*BUFSZ + (u64)bcl*32768;
                *(float2*)(op + (u64)v*64 + l) = make_float2(a0, a1);
                *(float2*)(op + (u64)(v+8)*64 + l) = make_float2(a2, a3);
            } else {
                const float* ap = g_pool + 12ULL*BUFSZ + (u64)bcl*32768;
                float bia = g_bias[bcl & 63];
                float* op = outp + (u64)bcl*32768;
                a0 += ap[(u64)v*64 + l] + bia;
                a1 += ap[(u64)v*64 + l + 1] + bia;
                a2 += ap[(u64)(v+8)*64 + l] + bia;
                a3 += ap[(u64)(v+8)*64 + l + 1] + bia;
                if (l < 58)     op[(u64)v*64 + l + 6]       = a0;
                if (l + 1 < 58) op[(u64)v*64 + l + 7]       = a1;
                if (l < 58)     op[(u64)(v+8)*64 + l + 6]   = a2;
                if (l + 1 < 58) op[(u64)(v+8)*64 + l + 7]   = a3;
            }
        }
    }
}

__global__ void k_zeropad(float* __restrict__ outp){
    int i = blockIdx.x*256 + threadIdx.x;
    if (i < 8*64*512*6){
        int row = i / 6, t = i - row*6;
        outp[(u64)row*64 + t] = 0.f;
    }
}

// ---------------------------------------------------------------------------
extern "C" void kernel_launch(void* const* d_in, const int* in_sizes, int n_in,
                              void* d_out, int out_size){
    (void)in_sizes; (void)n_in; (void)out_size;
    const float* x   = (const float*)d_in[0];
    const float* adj = (const float*)d_in[1];
    float* out = (float*)d_out;

    // allow >48KB dynamic smem for the node kernels (idempotent)
    cudaFuncSetAttribute(k_node_mma<0>, cudaFuncAttributeMaxDynamicSharedMemorySize, NODE_SMEM);
    cudaFuncSetAttribute(k_node_mma<1>, cudaFuncAttributeMaxDynamicSharedMemorySize, NODE_SMEM);
    cudaFuncSetAttribute(k_node_mma<2>, cudaFuncAttributeMaxDynamicSharedMemorySize, NODE_SMEM);

    k_deg  <<<512, 256>>>(adj);
    k_norm <<<512, 256>>>(adj);
    k_prepA<<<512, 256>>>();
    k_prep<<<64, 256>>>(
        (const float*)d_in[ 2], (const float*)d_in[ 3], (const float*)d_in[ 4], (const float*)d_in[ 5],
        (const float*)d_in[ 6], (const float*)d_in[ 7], (const float*)d_in[ 8], (const float*)d_in[ 9],
        (const float*)d_in[10], (const float*)d_in[11], (const float*)d_in[12], (const float*)d_in[13],
        (const float*)d_in[14], (const float*)d_in[15], (const float*)d_in[16], (const float*)d_in[17],
        (const float*)d_in[18], (const float*)d_in[19], (const float*)d_in[20], (const float*)d_in[21]);

    k_fused<<<4096, 128>>>(x);

    // Horner: branch0 seed slot 0 (q4), branch1 seed slot 6 (q9);
    // merged launches run both branches via gridDim.z = 2.
    dim3 ng3(256, 4, 2);
    k_node_mma<0><<<ng3, 256, NODE_SMEM>>>(0, 3, 0, 2, nullptr);   // step 0
    k_node_mma<0><<<ng3, 256, NODE_SMEM>>>(0, 2, 2, 4, nullptr);   // step 1
    k_node_mma<0><<<ng3, 256, NODE_SMEM>>>(0, 1, 4, 2, nullptr);   // step 2
    dim3 ng(256, 4, 1);
    k_node_mma<1><<<ng, 256, NODE_SMEM>>>(0, 0, 2, 0, nullptr);    // b0 final -> ACC
    k_node_mma<2><<<ng, 256, NODE_SMEM>>>(1, 5, 8, 0, out);        // b1 final -> out

    k_zeropad<<<6144, 256>>>(out);
}